// round 9
// baseline (speedup 1.0000x reference)
#include <cuda_runtime.h>
#include <cuda_fp16.h>
#include <stdint.h>

// ---------------- problem constants ----------------
namespace {
constexpr int T_  = 4096;
constexpr int D_  = 1024;
constexpr int E_  = 8;
constexpr int F_  = 2816;
constexpr int NP  = T_ * 2;       // 8192 (token,k) pairs
constexpr int N1  = 2 * F_;       // 5632
constexpr int BM  = 128;
constexpr int MAXTILES = 72;

// smem per k32-chunk buffer: A hi/lo 128x32 (8KB each) + B hi 256x32 (16KB)
constexpr int PLA  = 8192;
constexpr int PLB  = 16384;
constexpr int BUF  = 2 * PLA + PLB;   // 32768
constexpr int NBUF = 3;
constexpr int SMEM_DYN = NBUF * BUF;  // 98304 (>= staging 128*132*4 = 67584)

// prep region sizes (float4 units)
constexpr int N4_X   = T_ * D_ / 4;
constexpr int N4_GUP = (int)((size_t)E_ * N1 * D_ / 4);
constexpr int N4_DWN = (int)((size_t)E_ * D_ * F_ / 4);
constexpr int N4_OUT = T_ * D_ / 4;
constexpr int N4_TOTAL = N4_X + N4_GUP + N4_DWN + N4_OUT;
}

// ---------------- device scratch ----------------
__device__ __align__(16) __half g_x_hi[(size_t)T_ * D_];
__device__ __align__(16) __half g_x_lo[(size_t)T_ * D_];
__device__ __align__(16) __half g_gup_hi[(size_t)E_ * N1 * D_];
__device__ __align__(16) __half g_dwn_hi[(size_t)E_ * D_ * F_];
__device__ __align__(16) __half g_act_hi[(size_t)NP * F_];
__device__ __align__(16) __half g_act_lo[(size_t)NP * F_];

__device__ int g_rowtok[NP];
__device__ int g_rowpair[NP];
__device__ int g_tile_e[MAXTILES];
__device__ int g_tile_r0[MAXTILES];
__device__ int g_tile_rows[MAXTILES];
__device__ int g_ntiles;

// ---------------- helpers ----------------
__device__ __forceinline__ uint32_t smem_u32(const void* p) {
    uint32_t a;
    asm("{ .reg .u64 t; cvta.to.shared.u64 t, %1; cvt.u32.u64 %0, t; }" : "=r"(a) : "l"(p));
    return a;
}
__device__ __forceinline__ void split4h(float4 v, uint32_t& h0, uint32_t& h1,
                                        uint32_t& l0, uint32_t& l1) {
    __half2 H0 = __floats2half2_rn(v.x, v.y);
    __half2 H1 = __floats2half2_rn(v.z, v.w);
    float2 f0 = __half22float2(H0);
    float2 f1 = __half22float2(H1);
    __half2 L0 = __floats2half2_rn(v.x - f0.x, v.y - f0.y);
    __half2 L1 = __floats2half2_rn(v.z - f1.x, v.w - f1.y);
    h0 = *(uint32_t*)&H0; h1 = *(uint32_t*)&H1;
    l0 = *(uint32_t*)&L0; l1 = *(uint32_t*)&L1;
}
__device__ __forceinline__ void hi4h(float4 v, uint32_t& h0, uint32_t& h1) {
    __half2 H0 = __floats2half2_rn(v.x, v.y);
    __half2 H1 = __floats2half2_rn(v.z, v.w);
    h0 = *(uint32_t*)&H0; h1 = *(uint32_t*)&H1;
}
__device__ __forceinline__ void ldsm4(uint32_t& r0, uint32_t& r1, uint32_t& r2, uint32_t& r3,
                                      uint32_t addr) {
    asm volatile("ldmatrix.sync.aligned.m8n8.x4.shared.b16 {%0,%1,%2,%3}, [%4];"
                 : "=r"(r0), "=r"(r1), "=r"(r2), "=r"(r3) : "r"(addr));
}
__device__ __forceinline__ void mma16816(float* c, const uint32_t* a, uint32_t b0, uint32_t b1) {
    asm volatile(
        "mma.sync.aligned.m16n8k16.row.col.f32.f16.f16.f32 "
        "{%0,%1,%2,%3}, {%4,%5,%6,%7}, {%8,%9}, {%0,%1,%2,%3};"
        : "+f"(c[0]), "+f"(c[1]), "+f"(c[2]), "+f"(c[3])
        : "r"(a[0]), "r"(a[1]), "r"(a[2]), "r"(a[3]), "r"(b0), "r"(b1));
}
__device__ __forceinline__ void cp_async16(uint32_t dst, const void* src, int sz) {
    asm volatile("cp.async.cg.shared.global [%0], [%1], 16, %2;"
                 :: "r"(dst), "l"(src), "r"(sz) : "memory");
}
__device__ __forceinline__ void cp_commit() { asm volatile("cp.async.commit_group;" ::: "memory"); }
__device__ __forceinline__ void cp_wait0()  { asm volatile("cp.async.wait_group 0;" ::: "memory"); }
__device__ __forceinline__ void cp_wait1()  { asm volatile("cp.async.wait_group 1;" ::: "memory"); }
__device__ __forceinline__ void redadd(float* p, float v) {
    asm volatile("red.global.add.f32 [%0], %1;" :: "l"(p), "f"(v) : "memory");
}

// ---------------- merged single-block routing ----------------
__global__ void k_route(const int* __restrict__ ids) {
    __shared__ int scnt[E_];
    __shared__ int soff[E_ + 1];
    const int tid = threadIdx.x;
    if (tid < E_) scnt[tid] = 0;
    __syncthreads();

    int pe[NP / 1024], ps[NP / 1024];
#pragma unroll
    for (int t = 0; t < NP / 1024; t++) {
        int p = tid + t * 1024;
        int e = ids[p];
        e = e < 0 ? 0 : (e >= E_ ? E_ - 1 : e);
        pe[t] = e;
        ps[t] = atomicAdd(&scnt[e], 1);
    }
    __syncthreads();
    if (tid == 0) {
        int off = 0;
        soff[0] = 0;
        for (int e = 0; e < E_; e++) { off += scnt[e]; soff[e + 1] = off; }
        int nt = 0;
        for (int e = 0; e < E_; e++)
            for (int r0 = soff[e]; r0 < soff[e + 1]; r0 += BM) {
                g_tile_e[nt] = e; g_tile_r0[nt] = r0;
                int rem = soff[e + 1] - r0;
                g_tile_rows[nt] = rem < BM ? rem : BM;
                nt++;
            }
        g_ntiles = nt;
    }
    __syncthreads();
#pragma unroll
    for (int t = 0; t < NP / 1024; t++) {
        int p = tid + t * 1024;
        int gr = soff[pe[t]] + ps[t];
        g_rowtok[gr]  = p >> 1;
        g_rowpair[gr] = p;
    }
}

// ---------------- merged prep ----------------
__global__ void k_prep(const float4* __restrict__ x, const float4* __restrict__ gup,
                       const float4* __restrict__ dwn, float4* __restrict__ out) {
    int i = blockIdx.x * 256 + threadIdx.x;
    if (i < N4_X) {
        float4 v = x[i];
        uint32_t h0, h1, l0, l1;
        split4h(v, h0, h1, l0, l1);
        ((uint2*)g_x_hi)[i] = make_uint2(h0, h1);
        ((uint2*)g_x_lo)[i] = make_uint2(l0, l1);
        return;
    }
    i -= N4_X;
    if (i < N4_GUP) {
        float4 v = gup[i];
        uint32_t h0, h1;
        hi4h(v, h0, h1);
        ((uint2*)g_gup_hi)[i] = make_uint2(h0, h1);
        return;
    }
    i -= N4_GUP;
    if (i < N4_DWN) {
        float4 v = dwn[i];
        uint32_t h0, h1;
        hi4h(v, h0, h1);
        ((uint2*)g_dwn_hi)[i] = make_uint2(h0, h1);
        return;
    }
    i -= N4_DWN;
    if (i < N4_OUT) out[i] = make_float4(0.f, 0.f, 0.f, 0.f);
}

// ---------------- 2-product fp16 HMMA GEMM, block 128x256, warp 64x64 ----------------
// D = Ahi.Bhi + Alo.Bhi
// G1: 128 j per block (256 interleaved gate/up B-rows)   KDIM=1024
// G2: 256 n per block                                    KDIM=2816
template <bool G1>
__global__ void __launch_bounds__(256, 1)
moe_gemm_mma(const float* __restrict__ tw, float* __restrict__ outp) {
    constexpr int KDIM = G1 ? D_ : F_;
    constexpr int NC   = KDIM / 32;

    const int bt = blockIdx.y;
    if (bt >= g_ntiles) return;

    const int e    = g_tile_e[bt];
    const int row0 = g_tile_r0[bt];
    const int rows = g_tile_rows[bt];
    const int bn0  = blockIdx.x * (G1 ? 128 : 256);   // j-cols (G1) or n-cols (G2)

    const __half* __restrict__ Ah = G1 ? g_x_hi : g_act_hi;
    const __half* __restrict__ Al = G1 ? g_x_lo : g_act_lo;
    const size_t eoff = (size_t)e * (G1 ? (size_t)N1 * D_ : (size_t)D_ * F_);
    const __half* __restrict__ Bh = (G1 ? g_gup_hi : g_dwn_hi) + eoff;

    extern __shared__ __align__(16) char dynraw[];
    const uint32_t dynbase = smem_u32(dynraw);

    __shared__ int   s_map[BM];
    __shared__ int   s_out[BM];
    __shared__ float s_wt[BM];

    const int tid  = threadIdx.x;
    const int wid  = tid >> 5;
    const int lane = tid & 31;

    if (tid < BM) {
        int amap = -1, omap = -1;
        float w = 0.f;
        if (tid < rows) {
            if (G1) { amap = g_rowtok[row0 + tid]; omap = row0 + tid; }
            else    { amap = row0 + tid;           omap = g_rowpair[row0 + tid];
                      w = tw[omap]; }
        }
        s_map[tid] = amap; s_out[tid] = omap; s_wt[tid] = w;
    }
    __syncthreads();

    auto issue = [&](int c) {
        const uint32_t base = dynbase + (uint32_t)(c % NBUF) * BUF;
        const int kofs = c * 32;
        // A planes: 128 rows x 4 q units x 2 planes -> 4 per thread
#pragma unroll
        for (int t = 0; t < 2; t++) {
            int idx = tid + t * 256;
            int row = idx >> 2, q = idx & 3;
            int ar = s_map[row];
            int sz = ar >= 0 ? 16 : 0;
            size_t so = ((size_t)(ar < 0 ? 0 : ar) * KDIM + kofs) * 2 + q * 16;
            uint32_t doff = row * 64 + (((uint32_t)(q ^ (row & 3))) << 4);
            cp_async16(base + doff,       (const char*)Ah + so, sz);
            cp_async16(base + PLA + doff, (const char*)Al + so, sz);
        }
        // B plane: 256 rows x 4 q -> 4 per thread
#pragma unroll
        for (int t = 0; t < 4; t++) {
            int idx = tid + t * 256;
            int row = idx >> 2, q = idx & 3;
            int brow = G1 ? (bn0 + (row >> 1) + (row & 1) * F_) : (bn0 + row);
            size_t so = ((size_t)brow * KDIM + kofs) * 2 + q * 16;
            uint32_t doff = row * 64 + (((uint32_t)(q ^ (row & 3))) << 4);
            cp_async16(base + 2 * PLA + doff, (const char*)Bh + so, 16);
        }
        cp_commit();
    };

    // warp tile: 64 m x 64 n; warps 2m x 4n
    const int wm = (wid >> 2) * 64;
    const int wn = (wid & 3) * 64;
    const int lrow  = lane & 15;
    const int qhalf = lane >> 4;

    float acc[4][8][4];
#pragma unroll
    for (int i = 0; i < 4; i++)
#pragma unroll
        for (int j = 0; j < 8; j++)
#pragma unroll
            for (int k = 0; k < 4; k++) acc[i][j][k] = 0.f;

    issue(0);
    if (NC > 1) issue(1);

    for (int c = 0; c < NC; c++) {
        if (c + 1 < NC) cp_wait1();
        else            cp_wait0();
        __syncthreads();

        const uint32_t base = dynbase + (uint32_t)(c % NBUF) * BUF;
        const uint32_t ah = base, al = base + PLA, bh = base + 2 * PLA;

#pragma unroll
        for (int kk = 0; kk < 2; kk++) {
            const int qlog = kk * 2 + qhalf;
            uint32_t bfh[4][4];
#pragma unroll
            for (int g = 0; g < 4; g++) {
                int r = wn + g * 16 + lrow;
                uint32_t ao = (uint32_t)(r * 64 + ((qlog ^ (r & 3)) << 4));
                ldsm4(bfh[g][0], bfh[g][1], bfh[g][2], bfh[g][3], bh + ao);
            }
#pragma unroll
            for (int mi = 0; mi < 4; mi++) {
                int r = wm + mi * 16 + lrow;
                uint32_t ao = (uint32_t)(r * 64 + ((qlog ^ (r & 3)) << 4));
                uint32_t afh[4], afl[4];
                ldsm4(afh[0], afh[1], afh[2], afh[3], ah + ao);
                ldsm4(afl[0], afl[1], afl[2], afl[3], al + ao);
#pragma unroll
                for (int ni = 0; ni < 8; ni++) {
                    const int g = ni >> 1, sub = ni & 1;
                    mma16816(acc[mi][ni], afh, bfh[g][sub], bfh[g][sub + 2]);
                }
#pragma unroll
                for (int ni = 0; ni < 8; ni++) {
                    const int g = ni >> 1, sub = ni & 1;
                    mma16816(acc[mi][ni], afl, bfh[g][sub], bfh[g][sub + 2]);
                }
            }
        }
        if (c + 2 < NC) issue(c + 2);
    }
    __syncthreads();

    // ---- epilogue (96KB ring reused for staging) ----
    float* stg = (float*)dynraw;
    const int group = lane >> 2;
    const int tig   = lane & 3;

    if (G1) {
        // interleaved cols: acc[..][0]=gate(j), [1]=up(j); [2],[3] same at m+8
#pragma unroll
        for (int mi = 0; mi < 4; mi++) {
            int m = wm + mi * 16 + group;
#pragma unroll
            for (int ni = 0; ni < 8; ni++) {
                int j = (wn + ni * 8 + tig * 2) >> 1;   // 0..127
                float g0 = acc[mi][ni][0], u0 = acc[mi][ni][1];
                float g1 = acc[mi][ni][2], u1 = acc[mi][ni][3];
                stg[m * 132 + j]       = g0 / (1.f + __expf(-g0)) * u0;
                stg[(m + 8) * 132 + j] = g1 / (1.f + __expf(-g1)) * u1;
            }
        }
        __syncthreads();
        // store act 128 rows x 128 j (split hi/lo)
#pragma unroll
        for (int t = 0; t < 16; t++) {
            int idx = tid + t * 256;
            int row = idx >> 5, q = idx & 31;
            int orow = s_out[row];
            if (orow >= 0) {
                float4 v = *(const float4*)(stg + row * 132 + q * 4);
                uint32_t h0, h1, l0, l1;
                split4h(v, h0, h1, l0, l1);
                size_t ob = ((size_t)orow * F_ + bn0 + q * 4) * 2;
                *(uint2*)((char*)g_act_hi + ob) = make_uint2(h0, h1);
                *(uint2*)((char*)g_act_lo + ob) = make_uint2(l0, l1);
            }
        }
    } else {
        // two n-128 halves; weighted red.global.add into out[tok]
#pragma unroll
        for (int h = 0; h < 2; h++) {
            if (((wid & 3) >> 1) == h) {
#pragma unroll
                for (int mi = 0; mi < 4; mi++) {
                    int m = wm + mi * 16 + group;
#pragma unroll
                    for (int ni = 0; ni < 8; ni++) {
                        int n = wn + ni * 8 + tig * 2 - h * 128;   // 0..127
                        *(float2*)(stg + m * 132 + n)       = make_float2(acc[mi][ni][0], acc[mi][ni][1]);
                        *(float2*)(stg + (m + 8) * 132 + n) = make_float2(acc[mi][ni][2], acc[mi][ni][3]);
                    }
                }
            }
            __syncthreads();
#pragma unroll
            for (int t = 0; t < 16; t++) {
                int idx = tid + t * 256;
                int row = idx >> 5, q = idx & 31;
                int orow = s_out[row];
                if (orow >= 0) {
                    float4 v = *(const float4*)(stg + row * 132 + q * 4);
                    float w = s_wt[row];
                    float* op = outp + (size_t)(orow >> 1) * D_ + bn0 + h * 128 + q * 4;
                    redadd(op + 0, w * v.x);
                    redadd(op + 1, w * v.y);
                    redadd(op + 2, w * v.z);
                    redadd(op + 3, w * v.w);
                }
            }
            __syncthreads();
        }
    }
}

// ---------------- launch ----------------
extern "C" void kernel_launch(void* const* d_in, const int* in_sizes, int n_in,
                              void* d_out, int out_size) {
    const float* x   = (const float*)d_in[0];
    const float* gup = (const float*)d_in[1];
    const float* dwn = (const float*)d_in[2];
    const float* tw  = (const float*)d_in[3];
    const int*   ids = (const int*)d_in[4];
    float* out = (float*)d_out;

    cudaFuncSetAttribute(moe_gemm_mma<true>,  cudaFuncAttributeMaxDynamicSharedMemorySize, SMEM_DYN);
    cudaFuncSetAttribute(moe_gemm_mma<false>, cudaFuncAttributeMaxDynamicSharedMemorySize, SMEM_DYN);

    k_route<<<1, 1024>>>(ids);
    k_prep<<<(N4_TOTAL + 255) / 256, 256>>>((const float4*)x, (const float4*)gup,
                                            (const float4*)dwn, (float4*)out);

    moe_gemm_mma<true ><<<dim3(F_ / 128, MAXTILES), 256, SMEM_DYN>>>(tw, out);
    moe_gemm_mma<false><<<dim3(D_ / 256, MAXTILES), 256, SMEM_DYN>>>(tw, out);
}

// round 10
// speedup vs baseline: 1.0212x; 1.0212x over previous
#include <cuda_runtime.h>
#include <cuda_fp16.h>
#include <stdint.h>

// ---------------- problem constants ----------------
namespace {
constexpr int T_  = 4096;
constexpr int D_  = 1024;
constexpr int E_  = 8;
constexpr int F_  = 2816;
constexpr int NP  = T_ * 2;       // 8192 (token,k) pairs
constexpr int N1  = 2 * F_;       // 5632
constexpr int BM  = 128;
constexpr int MAXTILES = 72;
constexpr int NT  = 512;          // threads per GEMM block (16 warps)

// smem per k32-chunk buffer: A hi/lo 128x32 (8KB each) + B hi 256x32 (16KB)
constexpr int PLA  = 8192;
constexpr int PLB  = 16384;
constexpr int BUF  = 2 * PLA + PLB;   // 32768
constexpr int NBUF = 3;
constexpr int SMEM_DYN = NBUF * BUF;  // 98304 (>= staging 128*132*4 = 67584)

// prep region sizes (float4 units)
constexpr int N4_X   = T_ * D_ / 4;
constexpr int N4_GUP = (int)((size_t)E_ * N1 * D_ / 4);
constexpr int N4_DWN = (int)((size_t)E_ * D_ * F_ / 4);
constexpr int N4_OUT = T_ * D_ / 4;
constexpr int N4_TOTAL = N4_X + N4_GUP + N4_DWN + N4_OUT;
}

// ---------------- device scratch ----------------
__device__ __align__(16) __half g_x_hi[(size_t)T_ * D_];
__device__ __align__(16) __half g_x_lo[(size_t)T_ * D_];
__device__ __align__(16) __half g_gup_hi[(size_t)E_ * N1 * D_];
__device__ __align__(16) __half g_dwn_hi[(size_t)E_ * D_ * F_];
__device__ __align__(16) __half g_act_hi[(size_t)NP * F_];
__device__ __align__(16) __half g_act_lo[(size_t)NP * F_];

__device__ int g_rowtok[NP];
__device__ int g_rowpair[NP];
__device__ int g_tile_e[MAXTILES];
__device__ int g_tile_r0[MAXTILES];
__device__ int g_tile_rows[MAXTILES];
__device__ int g_ntiles;

// ---------------- helpers ----------------
__device__ __forceinline__ uint32_t smem_u32(const void* p) {
    uint32_t a;
    asm("{ .reg .u64 t; cvta.to.shared.u64 t, %1; cvt.u32.u64 %0, t; }" : "=r"(a) : "l"(p));
    return a;
}
__device__ __forceinline__ void split4h(float4 v, uint32_t& h0, uint32_t& h1,
                                        uint32_t& l0, uint32_t& l1) {
    __half2 H0 = __floats2half2_rn(v.x, v.y);
    __half2 H1 = __floats2half2_rn(v.z, v.w);
    float2 f0 = __half22float2(H0);
    float2 f1 = __half22float2(H1);
    __half2 L0 = __floats2half2_rn(v.x - f0.x, v.y - f0.y);
    __half2 L1 = __floats2half2_rn(v.z - f1.x, v.w - f1.y);
    h0 = *(uint32_t*)&H0; h1 = *(uint32_t*)&H1;
    l0 = *(uint32_t*)&L0; l1 = *(uint32_t*)&L1;
}
__device__ __forceinline__ void hi4h(float4 v, uint32_t& h0, uint32_t& h1) {
    __half2 H0 = __floats2half2_rn(v.x, v.y);
    __half2 H1 = __floats2half2_rn(v.z, v.w);
    h0 = *(uint32_t*)&H0; h1 = *(uint32_t*)&H1;
}
__device__ __forceinline__ void ldsm4(uint32_t& r0, uint32_t& r1, uint32_t& r2, uint32_t& r3,
                                      uint32_t addr) {
    asm volatile("ldmatrix.sync.aligned.m8n8.x4.shared.b16 {%0,%1,%2,%3}, [%4];"
                 : "=r"(r0), "=r"(r1), "=r"(r2), "=r"(r3) : "r"(addr));
}
__device__ __forceinline__ void mma16816(float* c, const uint32_t* a, uint32_t b0, uint32_t b1) {
    asm volatile(
        "mma.sync.aligned.m16n8k16.row.col.f32.f16.f16.f32 "
        "{%0,%1,%2,%3}, {%4,%5,%6,%7}, {%8,%9}, {%0,%1,%2,%3};"
        : "+f"(c[0]), "+f"(c[1]), "+f"(c[2]), "+f"(c[3])
        : "r"(a[0]), "r"(a[1]), "r"(a[2]), "r"(a[3]), "r"(b0), "r"(b1));
}
__device__ __forceinline__ void cp_async16(uint32_t dst, const void* src, int sz) {
    asm volatile("cp.async.cg.shared.global [%0], [%1], 16, %2;"
                 :: "r"(dst), "l"(src), "r"(sz) : "memory");
}
__device__ __forceinline__ void cp_commit() { asm volatile("cp.async.commit_group;" ::: "memory"); }
__device__ __forceinline__ void cp_wait0()  { asm volatile("cp.async.wait_group 0;" ::: "memory"); }
__device__ __forceinline__ void cp_wait1()  { asm volatile("cp.async.wait_group 1;" ::: "memory"); }
__device__ __forceinline__ void redadd(float* p, float v) {
    asm volatile("red.global.add.f32 [%0], %1;" :: "l"(p), "f"(v) : "memory");
}

// ---------------- merged single-block routing ----------------
__global__ void k_route(const int* __restrict__ ids) {
    __shared__ int scnt[E_];
    __shared__ int soff[E_ + 1];
    const int tid = threadIdx.x;
    if (tid < E_) scnt[tid] = 0;
    __syncthreads();

    int pe[NP / 1024], ps[NP / 1024];
#pragma unroll
    for (int t = 0; t < NP / 1024; t++) {
        int p = tid + t * 1024;
        int e = ids[p];
        e = e < 0 ? 0 : (e >= E_ ? E_ - 1 : e);
        pe[t] = e;
        ps[t] = atomicAdd(&scnt[e], 1);
    }
    __syncthreads();
    if (tid == 0) {
        int off = 0;
        soff[0] = 0;
        for (int e = 0; e < E_; e++) { off += scnt[e]; soff[e + 1] = off; }
        int nt = 0;
        for (int e = 0; e < E_; e++)
            for (int r0 = soff[e]; r0 < soff[e + 1]; r0 += BM) {
                g_tile_e[nt] = e; g_tile_r0[nt] = r0;
                int rem = soff[e + 1] - r0;
                g_tile_rows[nt] = rem < BM ? rem : BM;
                nt++;
            }
        g_ntiles = nt;
    }
    __syncthreads();
#pragma unroll
    for (int t = 0; t < NP / 1024; t++) {
        int p = tid + t * 1024;
        int gr = soff[pe[t]] + ps[t];
        g_rowtok[gr]  = p >> 1;
        g_rowpair[gr] = p;
    }
}

// ---------------- merged prep ----------------
__global__ void k_prep(const float4* __restrict__ x, const float4* __restrict__ gup,
                       const float4* __restrict__ dwn, float4* __restrict__ out) {
    int i = blockIdx.x * 256 + threadIdx.x;
    if (i < N4_X) {
        float4 v = x[i];
        uint32_t h0, h1, l0, l1;
        split4h(v, h0, h1, l0, l1);
        ((uint2*)g_x_hi)[i] = make_uint2(h0, h1);
        ((uint2*)g_x_lo)[i] = make_uint2(l0, l1);
        return;
    }
    i -= N4_X;
    if (i < N4_GUP) {
        float4 v = gup[i];
        uint32_t h0, h1;
        hi4h(v, h0, h1);
        ((uint2*)g_gup_hi)[i] = make_uint2(h0, h1);
        return;
    }
    i -= N4_GUP;
    if (i < N4_DWN) {
        float4 v = dwn[i];
        uint32_t h0, h1;
        hi4h(v, h0, h1);
        ((uint2*)g_dwn_hi)[i] = make_uint2(h0, h1);
        return;
    }
    i -= N4_DWN;
    if (i < N4_OUT) out[i] = make_float4(0.f, 0.f, 0.f, 0.f);
}

// ---------------- 2-product fp16 HMMA GEMM ----------------
// block 128x256, 16 warps (4m x 4n), warp tile 32x64
// D = Ahi.Bhi + Alo.Bhi
// G1: 128 j per block (256 interleaved gate/up B-rows)   KDIM=1024
// G2: 256 n per block                                    KDIM=2816
template <bool G1>
__global__ void __launch_bounds__(NT, 1)
moe_gemm_mma(const float* __restrict__ tw, float* __restrict__ outp) {
    constexpr int KDIM = G1 ? D_ : F_;
    constexpr int NC   = KDIM / 32;

    const int bt = blockIdx.y;
    if (bt >= g_ntiles) return;

    const int e    = g_tile_e[bt];
    const int row0 = g_tile_r0[bt];
    const int rows = g_tile_rows[bt];
    const int bn0  = blockIdx.x * (G1 ? 128 : 256);

    const __half* __restrict__ Ah = G1 ? g_x_hi : g_act_hi;
    const __half* __restrict__ Al = G1 ? g_x_lo : g_act_lo;
    const size_t eoff = (size_t)e * (G1 ? (size_t)N1 * D_ : (size_t)D_ * F_);
    const __half* __restrict__ Bh = (G1 ? g_gup_hi : g_dwn_hi) + eoff;

    extern __shared__ __align__(16) char dynraw[];
    const uint32_t dynbase = smem_u32(dynraw);

    __shared__ int   s_map[BM];
    __shared__ int   s_out[BM];
    __shared__ float s_wt[BM];

    const int tid  = threadIdx.x;
    const int wid  = tid >> 5;
    const int lane = tid & 31;

    if (tid < BM) {
        int amap = -1, omap = -1;
        float w = 0.f;
        if (tid < rows) {
            if (G1) { amap = g_rowtok[row0 + tid]; omap = row0 + tid; }
            else    { amap = row0 + tid;           omap = g_rowpair[row0 + tid];
                      w = tw[omap]; }
        }
        s_map[tid] = amap; s_out[tid] = omap; s_wt[tid] = w;
    }
    __syncthreads();

    auto issue = [&](int c) {
        const uint32_t base = dynbase + (uint32_t)(c % NBUF) * BUF;
        const int kofs = c * 32;
        // A planes: 128 rows x 4 q x 2 planes; 512 threads -> 1 row-unit each
        {
            int row = tid >> 2, q = tid & 3;
            int ar = s_map[row];
            int sz = ar >= 0 ? 16 : 0;
            size_t so = ((size_t)(ar < 0 ? 0 : ar) * KDIM + kofs) * 2 + q * 16;
            uint32_t doff = row * 64 + (((uint32_t)(q ^ (row & 3))) << 4);
            cp_async16(base + doff,       (const char*)Ah + so, sz);
            cp_async16(base + PLA + doff, (const char*)Al + so, sz);
        }
        // B plane: 256 rows x 4 q -> 2 per thread
#pragma unroll
        for (int t = 0; t < 2; t++) {
            int idx = tid + t * NT;
            int row = idx >> 2, q = idx & 3;
            int brow = G1 ? (bn0 + (row >> 1) + (row & 1) * F_) : (bn0 + row);
            size_t so = ((size_t)brow * KDIM + kofs) * 2 + q * 16;
            uint32_t doff = row * 64 + (((uint32_t)(q ^ (row & 3))) << 4);
            cp_async16(base + 2 * PLA + doff, (const char*)Bh + so, 16);
        }
        cp_commit();
    };

    // warp tile: 32 m x 64 n; warps: 4m x 4n
    const int wm = (wid >> 2) * 32;
    const int wn = (wid & 3) * 64;
    const int lrow  = lane & 15;
    const int qhalf = lane >> 4;

    float acc[2][8][4];
#pragma unroll
    for (int i = 0; i < 2; i++)
#pragma unroll
        for (int j = 0; j < 8; j++)
#pragma unroll
            for (int k = 0; k < 4; k++) acc[i][j][k] = 0.f;

    issue(0);
    if (NC > 1) issue(1);

    for (int c = 0; c < NC; c++) {
        if (c + 1 < NC) cp_wait1();
        else            cp_wait0();
        __syncthreads();

        const uint32_t base = dynbase + (uint32_t)(c % NBUF) * BUF;
        const uint32_t ah = base, al = base + PLA, bh = base + 2 * PLA;

#pragma unroll
        for (int kk = 0; kk < 2; kk++) {
            const int qlog = kk * 2 + qhalf;
            uint32_t bfh[4][4];
#pragma unroll
            for (int g = 0; g < 4; g++) {
                int r = wn + g * 16 + lrow;
                uint32_t ao = (uint32_t)(r * 64 + ((qlog ^ (r & 3)) << 4));
                ldsm4(bfh[g][0], bfh[g][1], bfh[g][2], bfh[g][3], bh + ao);
            }
#pragma unroll
            for (int mi = 0; mi < 2; mi++) {
                int r = wm + mi * 16 + lrow;
                uint32_t ao = (uint32_t)(r * 64 + ((qlog ^ (r & 3)) << 4));
                uint32_t afh[4], afl[4];
                ldsm4(afh[0], afh[1], afh[2], afh[3], ah + ao);
                ldsm4(afl[0], afl[1], afl[2], afl[3], al + ao);
#pragma unroll
                for (int ni = 0; ni < 8; ni++) {
                    const int g = ni >> 1, sub = ni & 1;
                    mma16816(acc[mi][ni], afh, bfh[g][sub], bfh[g][sub + 2]);
                }
#pragma unroll
                for (int ni = 0; ni < 8; ni++) {
                    const int g = ni >> 1, sub = ni & 1;
                    mma16816(acc[mi][ni], afl, bfh[g][sub], bfh[g][sub + 2]);
                }
            }
        }
        if (c + 2 < NC) issue(c + 2);
    }
    __syncthreads();

    // ---- epilogue (ring reused for staging) ----
    float* stg = (float*)dynraw;
    const int group = lane >> 2;
    const int tig   = lane & 3;

    if (G1) {
        // interleaved cols: acc[..][0]=gate(j), [1]=up(j); [2],[3] same at m+8
#pragma unroll
        for (int mi = 0; mi < 2; mi++) {
            int m = wm + mi * 16 + group;
#pragma unroll
            for (int ni = 0; ni < 8; ni++) {
                int j = (wn + ni * 8 + tig * 2) >> 1;   // 0..127
                float g0 = acc[mi][ni][0], u0 = acc[mi][ni][1];
                float g1 = acc[mi][ni][2], u1 = acc[mi][ni][3];
                stg[m * 132 + j]       = g0 / (1.f + __expf(-g0)) * u0;
                stg[(m + 8) * 132 + j] = g1 / (1.f + __expf(-g1)) * u1;
            }
        }
        __syncthreads();
        // store act 128 rows x 128 j (split hi/lo); 4096 float4 units / 512 thr
#pragma unroll
        for (int t = 0; t < 8; t++) {
            int idx = tid + t * NT;
            int row = idx >> 5, q = idx & 31;
            int orow = s_out[row];
            if (orow >= 0) {
                float4 v = *(const float4*)(stg + row * 132 + q * 4);
                uint32_t h0, h1, l0, l1;
                split4h(v, h0, h1, l0, l1);
                size_t ob = ((size_t)orow * F_ + bn0 + q * 4) * 2;
                *(uint2*)((char*)g_act_hi + ob) = make_uint2(h0, h1);
                *(uint2*)((char*)g_act_lo + ob) = make_uint2(l0, l1);
            }
        }
    } else {
        // two n-128 halves; weighted red.global.add into out[tok]
#pragma unroll
        for (int h = 0; h < 2; h++) {
            if (((wid & 3) >> 1) == h) {
#pragma unroll
                for (int mi = 0; mi < 2; mi++) {
                    int m = wm + mi * 16 + group;
#pragma unroll
                    for (int ni = 0; ni < 8; ni++) {
                        int n = wn + ni * 8 + tig * 2 - h * 128;   // 0..127
                        *(float2*)(stg + m * 132 + n)       = make_float2(acc[mi][ni][0], acc[mi][ni][1]);
                        *(float2*)(stg + (m + 8) * 132 + n) = make_float2(acc[mi][ni][2], acc[mi][ni][3]);
                    }
                }
            }
            __syncthreads();
#pragma unroll
            for (int t = 0; t < 8; t++) {
                int idx = tid + t * NT;
                int row = idx >> 5, q = idx & 31;
                int orow = s_out[row];
                if (orow >= 0) {
                    float4 v = *(const float4*)(stg + row * 132 + q * 4);
                    float w = s_wt[row];
                    float* op = outp + (size_t)(orow >> 1) * D_ + bn0 + h * 128 + q * 4;
                    redadd(op + 0, w * v.x);
                    redadd(op + 1, w * v.y);
                    redadd(op + 2, w * v.z);
                    redadd(op + 3, w * v.w);
                }
            }
            __syncthreads();
        }
    }
}

// ---------------- launch ----------------
extern "C" void kernel_launch(void* const* d_in, const int* in_sizes, int n_in,
                              void* d_out, int out_size) {
    const float* x   = (const float*)d_in[0];
    const float* gup = (const float*)d_in[1];
    const float* dwn = (const float*)d_in[2];
    const float* tw  = (const float*)d_in[3];
    const int*   ids = (const int*)d_in[4];
    float* out = (float*)d_out;

    cudaFuncSetAttribute(moe_gemm_mma<true>,  cudaFuncAttributeMaxDynamicSharedMemorySize, SMEM_DYN);
    cudaFuncSetAttribute(moe_gemm_mma<false>, cudaFuncAttributeMaxDynamicSharedMemorySize, SMEM_DYN);

    k_route<<<1, 1024>>>(ids);
    k_prep<<<(N4_TOTAL + 255) / 256, 256>>>((const float4*)x, (const float4*)gup,
                                            (const float4*)dwn, (float4*)out);

    moe_gemm_mma<true ><<<dim3(F_ / 128, MAXTILES), NT, SMEM_DYN>>>(tw, out);
    moe_gemm_mma<false><<<dim3(D_ / 256, MAXTILES), NT, SMEM_DYN>>>(tw, out);
}

// round 11
// speedup vs baseline: 1.1466x; 1.1228x over previous
#include <cuda_runtime.h>
#include <cuda_fp16.h>
#include <stdint.h>

// ---------------- problem constants ----------------
namespace {
constexpr int T_  = 4096;
constexpr int D_  = 1024;
constexpr int E_  = 8;
constexpr int F_  = 2816;
constexpr int NP  = T_ * 2;       // 8192 (token,k) pairs
constexpr int N1  = 2 * F_;       // 5632
constexpr int BM  = 128;
constexpr int MAXTILES = 72;

// smem: per k32-chunk buffer, 3 planes (Ah, Al, Bh) of 128x32 fp16 = 8KB each
constexpr int PL   = 8192;
constexpr int BUF  = 3 * PL;          // 24576 per buffer
constexpr int NBUF = 3;
constexpr int SMEM_DYN = NBUF * BUF;  // 73728 (>= G2 staging 128*132*4 = 67584)

// prep region sizes (float4 units)
constexpr int N4_X   = T_ * D_ / 4;
constexpr int N4_GUP = (int)((size_t)E_ * N1 * D_ / 4);
constexpr int N4_DWN = (int)((size_t)E_ * D_ * F_ / 4);
constexpr int N4_OUT = T_ * D_ / 4;
constexpr int N4_TOTAL = N4_X + N4_GUP + N4_DWN + N4_OUT;
}

// ---------------- device scratch ----------------
__device__ __align__(16) __half g_x_hi[(size_t)T_ * D_];
__device__ __align__(16) __half g_x_lo[(size_t)T_ * D_];
__device__ __align__(16) __half g_gup_hi[(size_t)E_ * N1 * D_];
__device__ __align__(16) __half g_dwn_hi[(size_t)E_ * D_ * F_];
__device__ __align__(16) __half g_act_hi[(size_t)NP * F_];
__device__ __align__(16) __half g_act_lo[(size_t)NP * F_];

__device__ int g_rowtok[NP];
__device__ int g_rowpair[NP];
__device__ int g_tile_e[MAXTILES];
__device__ int g_tile_r0[MAXTILES];
__device__ int g_tile_rows[MAXTILES];
__device__ int g_ntiles;

// ---------------- helpers ----------------
__device__ __forceinline__ uint32_t smem_u32(const void* p) {
    uint32_t a;
    asm("{ .reg .u64 t; cvta.to.shared.u64 t, %1; cvt.u32.u64 %0, t; }" : "=r"(a) : "l"(p));
    return a;
}
// conflict-free paired-row swizzle: tile row r (0..127), 16B unit q (0..3)
// smem row = r>>1 (128B); unit = ((r&1)*4 + q) ^ ((r>>1)&7)
// 8 consecutive r at fixed q -> 8 distinct 16B bank-groups.
__device__ __forceinline__ uint32_t sw(int r, int q) {
    return (uint32_t)(((r >> 1) << 7) | (((((r & 1) << 2) | q) ^ ((r >> 1) & 7)) << 4));
}
__device__ __forceinline__ void split4h(float4 v, uint32_t& h0, uint32_t& h1,
                                        uint32_t& l0, uint32_t& l1) {
    __half2 H0 = __floats2half2_rn(v.x, v.y);
    __half2 H1 = __floats2half2_rn(v.z, v.w);
    float2 f0 = __half22float2(H0);
    float2 f1 = __half22float2(H1);
    __half2 L0 = __floats2half2_rn(v.x - f0.x, v.y - f0.y);
    __half2 L1 = __floats2half2_rn(v.z - f1.x, v.w - f1.y);
    h0 = *(uint32_t*)&H0; h1 = *(uint32_t*)&H1;
    l0 = *(uint32_t*)&L0; l1 = *(uint32_t*)&L1;
}
__device__ __forceinline__ void hi4h(float4 v, uint32_t& h0, uint32_t& h1) {
    __half2 H0 = __floats2half2_rn(v.x, v.y);
    __half2 H1 = __floats2half2_rn(v.z, v.w);
    h0 = *(uint32_t*)&H0; h1 = *(uint32_t*)&H1;
}
__device__ __forceinline__ void ldsm4(uint32_t& r0, uint32_t& r1, uint32_t& r2, uint32_t& r3,
                                      uint32_t addr) {
    asm volatile("ldmatrix.sync.aligned.m8n8.x4.shared.b16 {%0,%1,%2,%3}, [%4];"
                 : "=r"(r0), "=r"(r1), "=r"(r2), "=r"(r3) : "r"(addr));
}
__device__ __forceinline__ void mma16816(float* c, const uint32_t* a, uint32_t b0, uint32_t b1) {
    asm volatile(
        "mma.sync.aligned.m16n8k16.row.col.f32.f16.f16.f32 "
        "{%0,%1,%2,%3}, {%4,%5,%6,%7}, {%8,%9}, {%0,%1,%2,%3};"
        : "+f"(c[0]), "+f"(c[1]), "+f"(c[2]), "+f"(c[3])
        : "r"(a[0]), "r"(a[1]), "r"(a[2]), "r"(a[3]), "r"(b0), "r"(b1));
}
__device__ __forceinline__ void cp_async16(uint32_t dst, const void* src, int sz) {
    asm volatile("cp.async.cg.shared.global [%0], [%1], 16, %2;"
                 :: "r"(dst), "l"(src), "r"(sz) : "memory");
}
__device__ __forceinline__ void cp_commit() { asm volatile("cp.async.commit_group;" ::: "memory"); }
__device__ __forceinline__ void cp_wait0()  { asm volatile("cp.async.wait_group 0;" ::: "memory"); }
__device__ __forceinline__ void cp_wait1()  { asm volatile("cp.async.wait_group 1;" ::: "memory"); }
__device__ __forceinline__ void redadd(float* p, float v) {
    asm volatile("red.global.add.f32 [%0], %1;" :: "l"(p), "f"(v) : "memory");
}

// ---------------- merged single-block routing ----------------
__global__ void k_route(const int* __restrict__ ids) {
    __shared__ int scnt[E_];
    __shared__ int soff[E_ + 1];
    const int tid = threadIdx.x;
    if (tid < E_) scnt[tid] = 0;
    __syncthreads();

    int pe[NP / 1024], ps[NP / 1024];
#pragma unroll
    for (int t = 0; t < NP / 1024; t++) {
        int p = tid + t * 1024;
        int e = ids[p];
        e = e < 0 ? 0 : (e >= E_ ? E_ - 1 : e);
        pe[t] = e;
        ps[t] = atomicAdd(&scnt[e], 1);
    }
    __syncthreads();
    if (tid == 0) {
        int off = 0;
        soff[0] = 0;
        for (int e = 0; e < E_; e++) { off += scnt[e]; soff[e + 1] = off; }
        int nt = 0;
        for (int e = 0; e < E_; e++)
            for (int r0 = soff[e]; r0 < soff[e + 1]; r0 += BM) {
                g_tile_e[nt] = e; g_tile_r0[nt] = r0;
                int rem = soff[e + 1] - r0;
                g_tile_rows[nt] = rem < BM ? rem : BM;
                nt++;
            }
        g_ntiles = nt;
    }
    __syncthreads();
#pragma unroll
    for (int t = 0; t < NP / 1024; t++) {
        int p = tid + t * 1024;
        int gr = soff[pe[t]] + ps[t];
        g_rowtok[gr]  = p >> 1;
        g_rowpair[gr] = p;
    }
}

// ---------------- merged prep ----------------
__global__ void k_prep(const float4* __restrict__ x, const float4* __restrict__ gup,
                       const float4* __restrict__ dwn, float4* __restrict__ out) {
    int i = blockIdx.x * 256 + threadIdx.x;
    if (i < N4_X) {
        float4 v = x[i];
        uint32_t h0, h1, l0, l1;
        split4h(v, h0, h1, l0, l1);
        ((uint2*)g_x_hi)[i] = make_uint2(h0, h1);
        ((uint2*)g_x_lo)[i] = make_uint2(l0, l1);
        return;
    }
    i -= N4_X;
    if (i < N4_GUP) {
        float4 v = gup[i];
        uint32_t h0, h1;
        hi4h(v, h0, h1);
        ((uint2*)g_gup_hi)[i] = make_uint2(h0, h1);
        return;
    }
    i -= N4_GUP;
    if (i < N4_DWN) {
        float4 v = dwn[i];
        uint32_t h0, h1;
        hi4h(v, h0, h1);
        ((uint2*)g_dwn_hi)[i] = make_uint2(h0, h1);
        return;
    }
    i -= N4_DWN;
    if (i < N4_OUT) out[i] = make_float4(0.f, 0.f, 0.f, 0.f);
}

// ---------------- 2-product fp16 HMMA grouped GEMM ----------------
// block 128x128, 8 warps (2m x 4n), warp 64x32, occ 2, 3-stage cp.async
// D = Ahi.Bhi + Alo.Bhi
// G1: 64 j per block (128 interleaved gate/up B-rows)  KDIM=1024
// G2: 128 n per block                                  KDIM=2816
template <bool G1>
__global__ void __launch_bounds__(256, 2)
moe_gemm_mma(const float* __restrict__ tw, float* __restrict__ outp) {
    constexpr int KDIM = G1 ? D_ : F_;
    constexpr int NC   = KDIM / 32;

    const int bt = blockIdx.y;
    if (bt >= g_ntiles) return;

    const int e    = g_tile_e[bt];
    const int row0 = g_tile_r0[bt];
    const int rows = g_tile_rows[bt];
    const int bn0  = blockIdx.x * (G1 ? 64 : 128);

    const __half* __restrict__ Ah = G1 ? g_x_hi : g_act_hi;
    const __half* __restrict__ Al = G1 ? g_x_lo : g_act_lo;
    const size_t eoff = (size_t)e * (G1 ? (size_t)N1 * D_ : (size_t)D_ * F_);
    const __half* __restrict__ Bh = (G1 ? g_gup_hi : g_dwn_hi) + eoff;

    extern __shared__ __align__(16) char dynraw[];
    const uint32_t dynbase = smem_u32(dynraw);

    __shared__ int   s_map[BM];
    __shared__ int   s_out[BM];
    __shared__ float s_wt[BM];

    const int tid  = threadIdx.x;
    const int wid  = tid >> 5;
    const int lane = tid & 31;

    if (tid < BM) {
        int amap = -1, omap = -1;
        float w = 0.f;
        if (tid < rows) {
            if (G1) { amap = g_rowtok[row0 + tid]; omap = row0 + tid; }
            else    { amap = row0 + tid;           omap = g_rowpair[row0 + tid];
                      w = tw[omap]; }
        }
        s_map[tid] = amap; s_out[tid] = omap; s_wt[tid] = w;
    }
    __syncthreads();

    // per-thread cp.async assignments (2 A row-units, 2 B row-units)
    const int rA0 = tid >> 2,         qA0 = tid & 3;
    const int rA1 = (tid + 256) >> 2, qA1 = tid & 3;

    auto issue = [&](int c) {
        const uint32_t base = dynbase + (uint32_t)(c % NBUF) * BUF;
        const int kofs = c * 32;
        {
            int ar = s_map[rA0];
            int sz = ar >= 0 ? 16 : 0;
            size_t so = ((size_t)(ar < 0 ? 0 : ar) * KDIM + kofs) * 2 + qA0 * 16;
            uint32_t doff = sw(rA0, qA0);
            cp_async16(base + doff,      (const char*)Ah + so, sz);
            cp_async16(base + PL + doff, (const char*)Al + so, sz);
        }
        {
            int ar = s_map[rA1];
            int sz = ar >= 0 ? 16 : 0;
            size_t so = ((size_t)(ar < 0 ? 0 : ar) * KDIM + kofs) * 2 + qA1 * 16;
            uint32_t doff = sw(rA1, qA1);
            cp_async16(base + doff,      (const char*)Ah + so, sz);
            cp_async16(base + PL + doff, (const char*)Al + so, sz);
        }
#pragma unroll
        for (int t = 0; t < 2; t++) {
            int idx = tid + t * 256;
            int row = idx >> 2, q = idx & 3;
            int brow = G1 ? (bn0 + (row >> 1) + (row & 1) * F_) : (bn0 + row);
            size_t so = ((size_t)brow * KDIM + kofs) * 2 + q * 16;
            uint32_t doff = sw(row, q);
            cp_async16(base + 2 * PL + doff, (const char*)Bh + so, 16);
        }
        cp_commit();
    };

    // warp tile: 64 m x 32 n
    const int wm = (wid >> 2) * 64;
    const int wn = (wid & 3) * 32;
    const int lrow  = lane & 15;
    const int qhalf = lane >> 4;     // 0/1 -> 16B half within k32

    float acc[4][4][4];
#pragma unroll
    for (int i = 0; i < 4; i++)
#pragma unroll
        for (int j = 0; j < 4; j++)
#pragma unroll
            for (int k = 0; k < 4; k++) acc[i][j][k] = 0.f;

    issue(0);
    if (NC > 1) issue(1);

    for (int c = 0; c < NC; c++) {
        if (c + 1 < NC) cp_wait1();
        else            cp_wait0();
        __syncthreads();   // stage c visible; all warps done with stage c-1

        const uint32_t base = dynbase + (uint32_t)(c % NBUF) * BUF;
        const uint32_t ah = base, al = base + PL, bh = base + 2 * PL;

#pragma unroll
        for (int kk = 0; kk < 2; kk++) {
            const int qlog = kk * 2 + qhalf;
            uint32_t bfh[2][4];
#pragma unroll
            for (int g = 0; g < 2; g++) {
                int r = wn + g * 16 + lrow;
                uint32_t ao = sw(r, qlog);
                ldsm4(bfh[g][0], bfh[g][1], bfh[g][2], bfh[g][3], bh + ao);
            }
#pragma unroll
            for (int mi = 0; mi < 4; mi++) {
                int r = wm + mi * 16 + lrow;
                uint32_t ao = sw(r, qlog);
                uint32_t afh[4], afl[4];
                ldsm4(afh[0], afh[1], afh[2], afh[3], ah + ao);
                ldsm4(afl[0], afl[1], afl[2], afl[3], al + ao);
                // product-major: same-acc MMAs 4 issues apart
#pragma unroll
                for (int ni = 0; ni < 4; ni++) {
                    const int g = ni >> 1, sub = ni & 1;
                    mma16816(acc[mi][ni], afh, bfh[g][sub], bfh[g][sub + 2]);
                }
#pragma unroll
                for (int ni = 0; ni < 4; ni++) {
                    const int g = ni >> 1, sub = ni & 1;
                    mma16816(acc[mi][ni], afl, bfh[g][sub], bfh[g][sub + 2]);
                }
            }
        }
        if (c + 2 < NC) issue(c + 2);
    }
    __syncthreads();

    // ---- epilogue (smem reused for staging) ----
    float* stg = (float*)dynraw;
    const int group = lane >> 2;
    const int tig   = lane & 3;

    if (G1) {
#pragma unroll
        for (int mi = 0; mi < 4; mi++) {
            int m = wm + mi * 16 + group;
#pragma unroll
            for (int ni = 0; ni < 4; ni++) {
                int j = (wid & 3) * 16 + ni * 4 + tig;
                float g0 = acc[mi][ni][0], u0 = acc[mi][ni][1];
                float g1 = acc[mi][ni][2], u1 = acc[mi][ni][3];
                stg[m * 68 + j]       = g0 / (1.f + __expf(-g0)) * u0;
                stg[(m + 8) * 68 + j] = g1 / (1.f + __expf(-g1)) * u1;
            }
        }
        __syncthreads();
#pragma unroll
        for (int t = 0; t < 8; t++) {
            int idx = tid + t * 256;
            int row = idx >> 4, q = idx & 15;
            int orow = s_out[row];
            if (orow >= 0) {
                float4 v = *(const float4*)(stg + row * 68 + q * 4);
                uint32_t h0, h1, l0, l1;
                split4h(v, h0, h1, l0, l1);
                size_t ob = ((size_t)orow * F_ + bn0 + q * 4) * 2;
                *(uint2*)((char*)g_act_hi + ob) = make_uint2(h0, h1);
                *(uint2*)((char*)g_act_lo + ob) = make_uint2(l0, l1);
            }
        }
    } else {
        // stage C, weighted red.global.add into out[tok] (2 contributions/elem)
#pragma unroll
        for (int mi = 0; mi < 4; mi++) {
            int m = wm + mi * 16 + group;
#pragma unroll
            for (int ni = 0; ni < 4; ni++) {
                int n = wn + ni * 8 + tig * 2;
                *(float2*)(stg + m * 132 + n)       = make_float2(acc[mi][ni][0], acc[mi][ni][1]);
                *(float2*)(stg + (m + 8) * 132 + n) = make_float2(acc[mi][ni][2], acc[mi][ni][3]);
            }
        }
        __syncthreads();
#pragma unroll
        for (int t = 0; t < 16; t++) {
            int idx = tid + t * 256;
            int row = idx >> 5, q = idx & 31;
            int orow = s_out[row];
            if (orow >= 0) {
                float4 v = *(const float4*)(stg + row * 132 + q * 4);
                float w = s_wt[row];
                float* op = outp + (size_t)(orow >> 1) * D_ + bn0 + q * 4;
                redadd(op + 0, w * v.x);
                redadd(op + 1, w * v.y);
                redadd(op + 2, w * v.z);
                redadd(op + 3, w * v.w);
            }
        }
    }
}

// ---------------- launch ----------------
extern "C" void kernel_launch(void* const* d_in, const int* in_sizes, int n_in,
                              void* d_out, int out_size) {
    const float* x   = (const float*)d_in[0];
    const float* gup = (const float*)d_in[1];
    const float* dwn = (const float*)d_in[2];
    const float* tw  = (const float*)d_in[3];
    const int*   ids = (const int*)d_in[4];
    float* out = (float*)d_out;

    cudaFuncSetAttribute(moe_gemm_mma<true>,  cudaFuncAttributeMaxDynamicSharedMemorySize, SMEM_DYN);
    cudaFuncSetAttribute(moe_gemm_mma<false>, cudaFuncAttributeMaxDynamicSharedMemorySize, SMEM_DYN);

    k_route<<<1, 1024>>>(ids);
    k_prep<<<(N4_TOTAL + 255) / 256, 256>>>((const float4*)x, (const float4*)gup,
                                            (const float4*)dwn, (float4*)out);

    moe_gemm_mma<true ><<<dim3(F_ / 64, MAXTILES), 256, SMEM_DYN>>>(tw, out);
    moe_gemm_mma<false><<<dim3(D_ / 128, MAXTILES), 256, SMEM_DYN>>>(tw, out);
}

// round 12
// speedup vs baseline: 1.7758x; 1.5488x over previous
#include <cuda_runtime.h>
#include <cuda_fp16.h>
#include <stdint.h>

// ---------------- problem constants ----------------
namespace {
constexpr int T_  = 4096;
constexpr int D_  = 1024;
constexpr int E_  = 8;
constexpr int F_  = 2816;
constexpr int NP  = T_ * 2;       // 8192 (token,k) pairs
constexpr int N1  = 2 * F_;       // 5632
constexpr int BM  = 128;
constexpr int MAXTILES = 72;

// smem per k32-chunk buffer: 2 planes (Ah, Bh) of 128x32 fp16 = 8KB each
constexpr int PL   = 8192;
constexpr int BUF  = 2 * PL;          // 16384 per buffer
constexpr int NBUF = 3;
constexpr int SMEM_DYN = 69632;       // >= G2 staging 128*132*4 = 67584 (> 3*BUF)

// prep region sizes (float4 units)
constexpr int N4_X   = T_ * D_ / 4;
constexpr int N4_GUP = (int)((size_t)E_ * N1 * D_ / 4);
constexpr int N4_DWN = (int)((size_t)E_ * D_ * F_ / 4);
constexpr int N4_OUT = T_ * D_ / 4;
constexpr int N4_TOTAL = N4_X + N4_GUP + N4_DWN + N4_OUT;
}

// ---------------- device scratch ----------------
__device__ __align__(16) __half g_x_hi[(size_t)T_ * D_];
__device__ __align__(16) __half g_gup_hi[(size_t)E_ * N1 * D_];
__device__ __align__(16) __half g_dwn_hi[(size_t)E_ * D_ * F_];
__device__ __align__(16) __half g_act_hi[(size_t)NP * F_];

__device__ int g_rowtok[NP];
__device__ int g_rowpair[NP];
__device__ int g_tile_e[MAXTILES];
__device__ int g_tile_r0[MAXTILES];
__device__ int g_tile_rows[MAXTILES];
__device__ int g_ntiles;

// ---------------- helpers ----------------
__device__ __forceinline__ uint32_t smem_u32(const void* p) {
    uint32_t a;
    asm("{ .reg .u64 t; cvta.to.shared.u64 t, %1; cvt.u32.u64 %0, t; }" : "=r"(a) : "l"(p));
    return a;
}
// conflict-free paired-row swizzle: tile row r (0..127), 16B unit q (0..3)
__device__ __forceinline__ uint32_t sw(int r, int q) {
    return (uint32_t)(((r >> 1) << 7) | (((((r & 1) << 2) | q) ^ ((r >> 1) & 7)) << 4));
}
__device__ __forceinline__ void hi4h(float4 v, uint32_t& h0, uint32_t& h1) {
    __half2 H0 = __floats2half2_rn(v.x, v.y);
    __half2 H1 = __floats2half2_rn(v.z, v.w);
    h0 = *(uint32_t*)&H0; h1 = *(uint32_t*)&H1;
}
__device__ __forceinline__ void ldsm4(uint32_t& r0, uint32_t& r1, uint32_t& r2, uint32_t& r3,
                                      uint32_t addr) {
    asm volatile("ldmatrix.sync.aligned.m8n8.x4.shared.b16 {%0,%1,%2,%3}, [%4];"
                 : "=r"(r0), "=r"(r1), "=r"(r2), "=r"(r3) : "r"(addr));
}
__device__ __forceinline__ void mma16816(float* c, const uint32_t* a, uint32_t b0, uint32_t b1) {
    asm volatile(
        "mma.sync.aligned.m16n8k16.row.col.f32.f16.f16.f32 "
        "{%0,%1,%2,%3}, {%4,%5,%6,%7}, {%8,%9}, {%0,%1,%2,%3};"
        : "+f"(c[0]), "+f"(c[1]), "+f"(c[2]), "+f"(c[3])
        : "r"(a[0]), "r"(a[1]), "r"(a[2]), "r"(a[3]), "r"(b0), "r"(b1));
}
__device__ __forceinline__ void cp_async16(uint32_t dst, const void* src, int sz) {
    asm volatile("cp.async.cg.shared.global [%0], [%1], 16, %2;"
                 :: "r"(dst), "l"(src), "r"(sz) : "memory");
}
__device__ __forceinline__ void cp_commit() { asm volatile("cp.async.commit_group;" ::: "memory"); }
__device__ __forceinline__ void cp_wait0()  { asm volatile("cp.async.wait_group 0;" ::: "memory"); }
__device__ __forceinline__ void cp_wait1()  { asm volatile("cp.async.wait_group 1;" ::: "memory"); }
__device__ __forceinline__ void redadd(float* p, float v) {
    asm volatile("red.global.add.f32 [%0], %1;" :: "l"(p), "f"(v) : "memory");
}

// ---------------- merged single-block routing ----------------
__global__ void k_route(const int* __restrict__ ids) {
    __shared__ int scnt[E_];
    __shared__ int soff[E_ + 1];
    const int tid = threadIdx.x;
    if (tid < E_) scnt[tid] = 0;
    __syncthreads();

    int pe[NP / 1024], ps[NP / 1024];
#pragma unroll
    for (int t = 0; t < NP / 1024; t++) {
        int p = tid + t * 1024;
        int e = ids[p];
        e = e < 0 ? 0 : (e >= E_ ? E_ - 1 : e);
        pe[t] = e;
        ps[t] = atomicAdd(&scnt[e], 1);
    }
    __syncthreads();
    if (tid == 0) {
        int off = 0;
        soff[0] = 0;
        for (int e = 0; e < E_; e++) { off += scnt[e]; soff[e + 1] = off; }
        int nt = 0;
        for (int e = 0; e < E_; e++)
            for (int r0 = soff[e]; r0 < soff[e + 1]; r0 += BM) {
                g_tile_e[nt] = e; g_tile_r0[nt] = r0;
                int rem = soff[e + 1] - r0;
                g_tile_rows[nt] = rem < BM ? rem : BM;
                nt++;
            }
        g_ntiles = nt;
    }
    __syncthreads();
#pragma unroll
    for (int t = 0; t < NP / 1024; t++) {
        int p = tid + t * 1024;
        int gr = soff[pe[t]] + ps[t];
        g_rowtok[gr]  = p >> 1;
        g_rowpair[gr] = p;
    }
}

// ---------------- merged prep: fp32 -> fp16 casts + d_out zeroing ----------------
__global__ void k_prep(const float4* __restrict__ x, const float4* __restrict__ gup,
                       const float4* __restrict__ dwn, float4* __restrict__ out) {
    int i = blockIdx.x * 256 + threadIdx.x;
    if (i < N4_X) {
        float4 v = x[i];
        uint32_t h0, h1;
        hi4h(v, h0, h1);
        ((uint2*)g_x_hi)[i] = make_uint2(h0, h1);
        return;
    }
    i -= N4_X;
    if (i < N4_GUP) {
        float4 v = gup[i];
        uint32_t h0, h1;
        hi4h(v, h0, h1);
        ((uint2*)g_gup_hi)[i] = make_uint2(h0, h1);
        return;
    }
    i -= N4_GUP;
    if (i < N4_DWN) {
        float4 v = dwn[i];
        uint32_t h0, h1;
        hi4h(v, h0, h1);
        ((uint2*)g_dwn_hi)[i] = make_uint2(h0, h1);
        return;
    }
    i -= N4_DWN;
    if (i < N4_OUT) out[i] = make_float4(0.f, 0.f, 0.f, 0.f);
}

// ---------------- pure fp16 HMMA grouped GEMM ----------------
// block 128x128, 8 warps (2m x 4n), warp 64x32, occ 2, 3-stage cp.async,
// conflict-free paired-row swizzle.
// G1: 64 j per block (128 interleaved gate/up B-rows)  KDIM=1024
// G2: 128 n per block                                  KDIM=2816
template <bool G1>
__global__ void __launch_bounds__(256, 2)
moe_gemm_mma(const float* __restrict__ tw, float* __restrict__ outp) {
    constexpr int KDIM = G1 ? D_ : F_;
    constexpr int NC   = KDIM / 32;

    const int bt = blockIdx.y;
    if (bt >= g_ntiles) return;

    const int e    = g_tile_e[bt];
    const int row0 = g_tile_r0[bt];
    const int rows = g_tile_rows[bt];
    const int bn0  = blockIdx.x * (G1 ? 64 : 128);

    const __half* __restrict__ Ah = G1 ? g_x_hi : g_act_hi;
    const size_t eoff = (size_t)e * (G1 ? (size_t)N1 * D_ : (size_t)D_ * F_);
    const __half* __restrict__ Bh = (G1 ? g_gup_hi : g_dwn_hi) + eoff;

    extern __shared__ __align__(16) char dynraw[];
    const uint32_t dynbase = smem_u32(dynraw);

    __shared__ int   s_map[BM];
    __shared__ int   s_out[BM];
    __shared__ float s_wt[BM];

    const int tid  = threadIdx.x;
    const int wid  = tid >> 5;
    const int lane = tid & 31;

    if (tid < BM) {
        int amap = -1, omap = -1;
        float w = 0.f;
        if (tid < rows) {
            if (G1) { amap = g_rowtok[row0 + tid]; omap = row0 + tid; }
            else    { amap = row0 + tid;           omap = g_rowpair[row0 + tid];
                      w = tw[omap]; }
        }
        s_map[tid] = amap; s_out[tid] = omap; s_wt[tid] = w;
    }
    __syncthreads();

    // per-thread cp.async: 2 A row-units + 2 B row-units
    const int rA0 = tid >> 2,         qA0 = tid & 3;
    const int rA1 = (tid + 256) >> 2, qA1 = tid & 3;

    auto issue = [&](int c) {
        const uint32_t base = dynbase + (uint32_t)(c % NBUF) * BUF;
        const int kofs = c * 32;
        {
            int ar = s_map[rA0];
            int sz = ar >= 0 ? 16 : 0;
            size_t so = ((size_t)(ar < 0 ? 0 : ar) * KDIM + kofs) * 2 + qA0 * 16;
            cp_async16(base + sw(rA0, qA0), (const char*)Ah + so, sz);
        }
        {
            int ar = s_map[rA1];
            int sz = ar >= 0 ? 16 : 0;
            size_t so = ((size_t)(ar < 0 ? 0 : ar) * KDIM + kofs) * 2 + qA1 * 16;
            cp_async16(base + sw(rA1, qA1), (const char*)Ah + so, sz);
        }
#pragma unroll
        for (int t = 0; t < 2; t++) {
            int idx = tid + t * 256;
            int row = idx >> 2, q = idx & 3;
            int brow = G1 ? (bn0 + (row >> 1) + (row & 1) * F_) : (bn0 + row);
            size_t so = ((size_t)brow * KDIM + kofs) * 2 + q * 16;
            cp_async16(base + PL + sw(row, q), (const char*)Bh + so, 16);
        }
        cp_commit();
    };

    // warp tile: 64 m x 32 n
    const int wm = (wid >> 2) * 64;
    const int wn = (wid & 3) * 32;
    const int lrow  = lane & 15;
    const int qhalf = lane >> 4;

    float acc[4][4][4];
#pragma unroll
    for (int i = 0; i < 4; i++)
#pragma unroll
        for (int j = 0; j < 4; j++)
#pragma unroll
            for (int k = 0; k < 4; k++) acc[i][j][k] = 0.f;

    issue(0);
    if (NC > 1) issue(1);

    for (int c = 0; c < NC; c++) {
        if (c + 1 < NC) cp_wait1();
        else            cp_wait0();
        __syncthreads();   // stage c visible; all warps done with stage c-1

        const uint32_t base = dynbase + (uint32_t)(c % NBUF) * BUF;
        const uint32_t ah = base, bh = base + PL;

#pragma unroll
        for (int kk = 0; kk < 2; kk++) {
            const int qlog = kk * 2 + qhalf;
            uint32_t bfh[2][4];
#pragma unroll
            for (int g = 0; g < 2; g++) {
                int r = wn + g * 16 + lrow;
                ldsm4(bfh[g][0], bfh[g][1], bfh[g][2], bfh[g][3], bh + sw(r, qlog));
            }
#pragma unroll
            for (int mi = 0; mi < 4; mi++) {
                int r = wm + mi * 16 + lrow;
                uint32_t afh[4];
                ldsm4(afh[0], afh[1], afh[2], afh[3], ah + sw(r, qlog));
#pragma unroll
                for (int ni = 0; ni < 4; ni++) {
                    const int g = ni >> 1, sub = ni & 1;
                    mma16816(acc[mi][ni], afh, bfh[g][sub], bfh[g][sub + 2]);
                }
            }
        }
        if (c + 2 < NC) issue(c + 2);
    }
    __syncthreads();

    // ---- epilogue (smem reused for staging) ----
    float* stg = (float*)dynraw;
    const int group = lane >> 2;
    const int tig   = lane & 3;

    if (G1) {
#pragma unroll
        for (int mi = 0; mi < 4; mi++) {
            int m = wm + mi * 16 + group;
#pragma unroll
            for (int ni = 0; ni < 4; ni++) {
                int j = (wid & 3) * 16 + ni * 4 + tig;
                float g0 = acc[mi][ni][0], u0 = acc[mi][ni][1];
                float g1 = acc[mi][ni][2], u1 = acc[mi][ni][3];
                stg[m * 68 + j]       = g0 / (1.f + __expf(-g0)) * u0;
                stg[(m + 8) * 68 + j] = g1 / (1.f + __expf(-g1)) * u1;
            }
        }
        __syncthreads();
#pragma unroll
        for (int t = 0; t < 8; t++) {
            int idx = tid + t * 256;
            int row = idx >> 4, q = idx & 15;
            int orow = s_out[row];
            if (orow >= 0) {
                float4 v = *(const float4*)(stg + row * 68 + q * 4);
                uint32_t h0, h1;
                hi4h(v, h0, h1);
                size_t ob = ((size_t)orow * F_ + bn0 + q * 4) * 2;
                *(uint2*)((char*)g_act_hi + ob) = make_uint2(h0, h1);
            }
        }
    } else {
        // stage C, weighted red.global.add into out[tok] (2 contributions/elem)
#pragma unroll
        for (int mi = 0; mi < 4; mi++) {
            int m = wm + mi * 16 + group;
#pragma unroll
            for (int ni = 0; ni < 4; ni++) {
                int n = wn + ni * 8 + tig * 2;
                *(float2*)(stg + m * 132 + n)       = make_float2(acc[mi][ni][0], acc[mi][ni][1]);
                *(float2*)(stg + (m + 8) * 132 + n) = make_float2(acc[mi][ni][2], acc[mi][ni][3]);
            }
        }
        __syncthreads();
#pragma unroll
        for (int t = 0; t < 16; t++) {
            int idx = tid + t * 256;
            int row = idx >> 5, q = idx & 31;
            int orow = s_out[row];
            if (orow >= 0) {
                float4 v = *(const float4*)(stg + row * 132 + q * 4);
                float w = s_wt[row];
                float* op = outp + (size_t)(orow >> 1) * D_ + bn0 + q * 4;
                redadd(op + 0, w * v.x);
                redadd(op + 1, w * v.y);
                redadd(op + 2, w * v.z);
                redadd(op + 3, w * v.w);
            }
        }
    }
}

// ---------------- launch ----------------
extern "C" void kernel_launch(void* const* d_in, const int* in_sizes, int n_in,
                              void* d_out, int out_size) {
    const float* x   = (const float*)d_in[0];
    const float* gup = (const float*)d_in[1];
    const float* dwn = (const float*)d_in[2];
    const float* tw  = (const float*)d_in[3];
    const int*   ids = (const int*)d_in[4];
    float* out = (float*)d_out;

    cudaFuncSetAttribute(moe_gemm_mma<true>,  cudaFuncAttributeMaxDynamicSharedMemorySize, SMEM_DYN);
    cudaFuncSetAttribute(moe_gemm_mma<false>, cudaFuncAttributeMaxDynamicSharedMemorySize, SMEM_DYN);

    k_route<<<1, 1024>>>(ids);
    k_prep<<<(N4_TOTAL + 255) / 256, 256>>>((const float4*)x, (const float4*)gup,
                                            (const float4*)dwn, (float4*)out);

    moe_gemm_mma<true ><<<dim3(F_ / 64, MAXTILES), 256, SMEM_DYN>>>(tw, out);
    moe_gemm_mma<false><<<dim3(D_ / 128, MAXTILES), 256, SMEM_DYN>>>(tw, out);
}

// round 13
// speedup vs baseline: 1.9615x; 1.1045x over previous
#include <cuda_runtime.h>
#include <cuda_fp16.h>
#include <stdint.h>

// ---------------- problem constants ----------------
namespace {
constexpr int T_  = 4096;
constexpr int D_  = 1024;
constexpr int E_  = 8;
constexpr int F_  = 2816;
constexpr int NP  = T_ * 2;       // 8192 (token,k) pairs
constexpr int N1  = 2 * F_;       // 5632
constexpr int BM  = 128;
constexpr int MAXTILES = 72;

// smem per k64-chunk buffer: 2 planes (Ah, Bh) of 128x64 fp16 = 16KB each
constexpr int PL   = 16384;
constexpr int BUF  = 2 * PL;          // 32768 per buffer
constexpr int NBUF = 3;
constexpr int SMEM_DYN = NBUF * BUF;  // 98304 (>= G2 staging 67584)

// prep region sizes (float4 units)
constexpr int N4_X   = T_ * D_ / 4;
constexpr int N4_GUP = (int)((size_t)E_ * N1 * D_ / 4);
constexpr int N4_DWN = (int)((size_t)E_ * D_ * F_ / 4);
constexpr int N4_OUT = T_ * D_ / 4;
constexpr int N4_TOTAL = N4_X + N4_GUP + N4_DWN + N4_OUT;
}

// ---------------- device scratch ----------------
__device__ __align__(16) __half g_x_hi[(size_t)T_ * D_];
__device__ __align__(16) __half g_gup_hi[(size_t)E_ * N1 * D_];
__device__ __align__(16) __half g_dwn_hi[(size_t)E_ * D_ * F_];
__device__ __align__(16) __half g_act_hi[(size_t)NP * F_];

__device__ int g_rowtok[NP];
__device__ int g_rowpair[NP];
__device__ int g_tile_e[MAXTILES];
__device__ int g_tile_r0[MAXTILES];
__device__ int g_tile_rows[MAXTILES];
__device__ int g_ntiles;

// ---------------- helpers ----------------
__device__ __forceinline__ uint32_t smem_u32(const void* p) {
    uint32_t a;
    asm("{ .reg .u64 t; cvta.to.shared.u64 t, %1; cvt.u32.u64 %0, t; }" : "=r"(a) : "l"(p));
    return a;
}
// SW128 swizzle: tile row r (0..127) = one 128B smem row; 16B unit q (0..7)
__device__ __forceinline__ uint32_t sw(int r, int q) {
    return (uint32_t)((r << 7) | (((q ^ (r & 7))) << 4));
}
__device__ __forceinline__ void hi4h(float4 v, uint32_t& h0, uint32_t& h1) {
    __half2 H0 = __floats2half2_rn(v.x, v.y);
    __half2 H1 = __floats2half2_rn(v.z, v.w);
    h0 = *(uint32_t*)&H0; h1 = *(uint32_t*)&H1;
}
__device__ __forceinline__ void ldsm4(uint32_t& r0, uint32_t& r1, uint32_t& r2, uint32_t& r3,
                                      uint32_t addr) {
    asm volatile("ldmatrix.sync.aligned.m8n8.x4.shared.b16 {%0,%1,%2,%3}, [%4];"
                 : "=r"(r0), "=r"(r1), "=r"(r2), "=r"(r3) : "r"(addr));
}
__device__ __forceinline__ void mma16816(float* c, const uint32_t* a, uint32_t b0, uint32_t b1) {
    asm volatile(
        "mma.sync.aligned.m16n8k16.row.col.f32.f16.f16.f32 "
        "{%0,%1,%2,%3}, {%4,%5,%6,%7}, {%8,%9}, {%0,%1,%2,%3};"
        : "+f"(c[0]), "+f"(c[1]), "+f"(c[2]), "+f"(c[3])
        : "r"(a[0]), "r"(a[1]), "r"(a[2]), "r"(a[3]), "r"(b0), "r"(b1));
}
__device__ __forceinline__ void cp_async16(uint32_t dst, const void* src, int sz) {
    asm volatile("cp.async.cg.shared.global [%0], [%1], 16, %2;"
                 :: "r"(dst), "l"(src), "r"(sz) : "memory");
}
__device__ __forceinline__ void cp_commit() { asm volatile("cp.async.commit_group;" ::: "memory"); }
__device__ __forceinline__ void cp_wait0()  { asm volatile("cp.async.wait_group 0;" ::: "memory"); }
__device__ __forceinline__ void cp_wait1()  { asm volatile("cp.async.wait_group 1;" ::: "memory"); }
__device__ __forceinline__ void redadd(float* p, float v) {
    asm volatile("red.global.add.f32 [%0], %1;" :: "l"(p), "f"(v) : "memory");
}

// ---------------- merged single-block routing ----------------
__global__ void k_route(const int* __restrict__ ids) {
    __shared__ int scnt[E_];
    __shared__ int soff[E_ + 1];
    const int tid = threadIdx.x;
    if (tid < E_) scnt[tid] = 0;
    __syncthreads();

    int pe[NP / 1024], ps[NP / 1024];
#pragma unroll
    for (int t = 0; t < NP / 1024; t++) {
        int p = tid + t * 1024;
        int e = ids[p];
        e = e < 0 ? 0 : (e >= E_ ? E_ - 1 : e);
        pe[t] = e;
        ps[t] = atomicAdd(&scnt[e], 1);
    }
    __syncthreads();
    if (tid == 0) {
        int off = 0;
        soff[0] = 0;
        for (int e = 0; e < E_; e++) { off += scnt[e]; soff[e + 1] = off; }
        int nt = 0;
        for (int e = 0; e < E_; e++)
            for (int r0 = soff[e]; r0 < soff[e + 1]; r0 += BM) {
                g_tile_e[nt] = e; g_tile_r0[nt] = r0;
                int rem = soff[e + 1] - r0;
                g_tile_rows[nt] = rem < BM ? rem : BM;
                nt++;
            }
        g_ntiles = nt;
    }
    __syncthreads();
#pragma unroll
    for (int t = 0; t < NP / 1024; t++) {
        int p = tid + t * 1024;
        int gr = soff[pe[t]] + ps[t];
        g_rowtok[gr]  = p >> 1;
        g_rowpair[gr] = p;
    }
}

// ---------------- merged prep: fp32 -> fp16 casts + d_out zeroing ----------------
__global__ void k_prep(const float4* __restrict__ x, const float4* __restrict__ gup,
                       const float4* __restrict__ dwn, float4* __restrict__ out) {
    int i = blockIdx.x * 256 + threadIdx.x;
    if (i < N4_X) {
        float4 v = x[i];
        uint32_t h0, h1;
        hi4h(v, h0, h1);
        ((uint2*)g_x_hi)[i] = make_uint2(h0, h1);
        return;
    }
    i -= N4_X;
    if (i < N4_GUP) {
        float4 v = gup[i];
        uint32_t h0, h1;
        hi4h(v, h0, h1);
        ((uint2*)g_gup_hi)[i] = make_uint2(h0, h1);
        return;
    }
    i -= N4_GUP;
    if (i < N4_DWN) {
        float4 v = dwn[i];
        uint32_t h0, h1;
        hi4h(v, h0, h1);
        ((uint2*)g_dwn_hi)[i] = make_uint2(h0, h1);
        return;
    }
    i -= N4_DWN;
    if (i < N4_OUT) out[i] = make_float4(0.f, 0.f, 0.f, 0.f);
}

// ---------------- pure fp16 HMMA grouped GEMM, BK=64 chunks ----------------
// block 128x128, 8 warps (2m x 4n), warp 64x32, occ 2, 3-stage cp.async,
// SW128 swizzle (128B rows), one barrier per 64 k.
// G1: 64 j per block (128 interleaved gate/up B-rows)  KDIM=1024, NC=16
// G2: 128 n per block                                  KDIM=2816, NC=44
template <bool G1>
__global__ void __launch_bounds__(256, 2)
moe_gemm_mma(const float* __restrict__ tw, float* __restrict__ outp) {
    constexpr int KDIM = G1 ? D_ : F_;
    constexpr int NC   = KDIM / 64;

    const int bt = blockIdx.y;
    if (bt >= g_ntiles) return;

    const int e    = g_tile_e[bt];
    const int row0 = g_tile_r0[bt];
    const int rows = g_tile_rows[bt];
    const int bn0  = blockIdx.x * (G1 ? 64 : 128);

    const __half* __restrict__ Ah = G1 ? g_x_hi : g_act_hi;
    const size_t eoff = (size_t)e * (G1 ? (size_t)N1 * D_ : (size_t)D_ * F_);
    const __half* __restrict__ Bh = (G1 ? g_gup_hi : g_dwn_hi) + eoff;

    extern __shared__ __align__(16) char dynraw[];
    const uint32_t dynbase = smem_u32(dynraw);

    __shared__ int   s_map[BM];
    __shared__ int   s_out[BM];
    __shared__ float s_wt[BM];

    const int tid  = threadIdx.x;
    const int wid  = tid >> 5;
    const int lane = tid & 31;

    if (tid < BM) {
        int amap = -1, omap = -1;
        float w = 0.f;
        if (tid < rows) {
            if (G1) { amap = g_rowtok[row0 + tid]; omap = row0 + tid; }
            else    { amap = row0 + tid;           omap = g_rowpair[row0 + tid];
                      w = tw[omap]; }
        }
        s_map[tid] = amap; s_out[tid] = omap; s_wt[tid] = w;
    }
    __syncthreads();

    // per-thread cp.async: 4 A units + 4 B units (16B each)
    // A/B unit u = tid + t*256: row = u>>3, q = u&7
    auto issue = [&](int c) {
        const uint32_t base = dynbase + (uint32_t)(c % NBUF) * BUF;
        const int kofs = c * 64;
#pragma unroll
        for (int t = 0; t < 4; t++) {
            int u = tid + t * 256;
            int row = u >> 3, q = u & 7;
            int ar = s_map[row];
            int sz = ar >= 0 ? 16 : 0;
            size_t so = ((size_t)(ar < 0 ? 0 : ar) * KDIM + kofs) * 2 + q * 16;
            cp_async16(base + sw(row, q), (const char*)Ah + so, sz);
        }
#pragma unroll
        for (int t = 0; t < 4; t++) {
            int u = tid + t * 256;
            int row = u >> 3, q = u & 7;
            int brow = G1 ? (bn0 + (row >> 1) + (row & 1) * F_) : (bn0 + row);
            size_t so = ((size_t)brow * KDIM + kofs) * 2 + q * 16;
            cp_async16(base + PL + sw(row, q), (const char*)Bh + so, 16);
        }
        cp_commit();
    };

    // warp tile: 64 m x 32 n
    const int wm = (wid >> 2) * 64;
    const int wn = (wid & 3) * 32;
    const int lrow  = lane & 15;
    const int qhalf = lane >> 4;     // 0/1 -> 16B half within each k32

    float acc[4][4][4];
#pragma unroll
    for (int i = 0; i < 4; i++)
#pragma unroll
        for (int j = 0; j < 4; j++)
#pragma unroll
            for (int k = 0; k < 4; k++) acc[i][j][k] = 0.f;

    issue(0);
    if (NC > 1) issue(1);

    for (int c = 0; c < NC; c++) {
        if (c + 1 < NC) cp_wait1();
        else            cp_wait0();
        __syncthreads();   // stage c visible; all warps done with stage c-1

        const uint32_t base = dynbase + (uint32_t)(c % NBUF) * BUF;
        const uint32_t ah = base, bh = base + PL;

#pragma unroll
        for (int kk = 0; kk < 4; kk++) {          // 4 k16 steps per 64-chunk
            const int qlog = kk * 2 + qhalf;      // 16B unit 0..7
            uint32_t bfh[2][4];
#pragma unroll
            for (int g = 0; g < 2; g++) {
                int r = wn + g * 16 + lrow;
                ldsm4(bfh[g][0], bfh[g][1], bfh[g][2], bfh[g][3], bh + sw(r, qlog));
            }
#pragma unroll
            for (int mi = 0; mi < 4; mi++) {
                int r = wm + mi * 16 + lrow;
                uint32_t afh[4];
                ldsm4(afh[0], afh[1], afh[2], afh[3], ah + sw(r, qlog));
#pragma unroll
                for (int ni = 0; ni < 4; ni++) {
                    const int g = ni >> 1, sub = ni & 1;
                    mma16816(acc[mi][ni], afh, bfh[g][sub], bfh[g][sub + 2]);
                }
            }
        }
        if (c + 2 < NC) issue(c + 2);
    }
    __syncthreads();

    // ---- epilogue (smem reused for staging) ----
    float* stg = (float*)dynraw;
    const int group = lane >> 2;
    const int tig   = lane & 3;

    if (G1) {
#pragma unroll
        for (int mi = 0; mi < 4; mi++) {
            int m = wm + mi * 16 + group;
#pragma unroll
            for (int ni = 0; ni < 4; ni++) {
                int j = (wid & 3) * 16 + ni * 4 + tig;
                float g0 = acc[mi][ni][0], u0 = acc[mi][ni][1];
                float g1 = acc[mi][ni][2], u1 = acc[mi][ni][3];
                stg[m * 68 + j]       = g0 / (1.f + __expf(-g0)) * u0;
                stg[(m + 8) * 68 + j] = g1 / (1.f + __expf(-g1)) * u1;
            }
        }
        __syncthreads();
#pragma unroll
        for (int t = 0; t < 8; t++) {
            int idx = tid + t * 256;
            int row = idx >> 4, q = idx & 15;
            int orow = s_out[row];
            if (orow >= 0) {
                float4 v = *(const float4*)(stg + row * 68 + q * 4);
                uint32_t h0, h1;
                hi4h(v, h0, h1);
                size_t ob = ((size_t)orow * F_ + bn0 + q * 4) * 2;
                *(uint2*)((char*)g_act_hi + ob) = make_uint2(h0, h1);
            }
        }
    } else {
        // stage C, weighted red.global.add into out[tok] (2 contributions/elem)
#pragma unroll
        for (int mi = 0; mi < 4; mi++) {
            int m = wm + mi * 16 + group;
#pragma unroll
            for (int ni = 0; ni < 4; ni++) {
                int n = wn + ni * 8 + tig * 2;
                *(float2*)(stg + m * 132 + n)       = make_float2(acc[mi][ni][0], acc[mi][ni][1]);
                *(float2*)(stg + (m + 8) * 132 + n) = make_float2(acc[mi][ni][2], acc[mi][ni][3]);
            }
        }
        __syncthreads();
#pragma unroll
        for (int t = 0; t < 16; t++) {
            int idx = tid + t * 256;
            int row = idx >> 5, q = idx & 31;
            int orow = s_out[row];
            if (orow >= 0) {
                float4 v = *(const float4*)(stg + row * 132 + q * 4);
                float w = s_wt[row];
                float* op = outp + (size_t)(orow >> 1) * D_ + bn0 + q * 4;
                redadd(op + 0, w * v.x);
                redadd(op + 1, w * v.y);
                redadd(op + 2, w * v.z);
                redadd(op + 3, w * v.w);
            }
        }
    }
}

// ---------------- launch ----------------
extern "C" void kernel_launch(void* const* d_in, const int* in_sizes, int n_in,
                              void* d_out, int out_size) {
    const float* x   = (const float*)d_in[0];
    const float* gup = (const float*)d_in[1];
    const float* dwn = (const float*)d_in[2];
    const float* tw  = (const float*)d_in[3];
    const int*   ids = (const int*)d_in[4];
    float* out = (float*)d_out;

    cudaFuncSetAttribute(moe_gemm_mma<true>,  cudaFuncAttributeMaxDynamicSharedMemorySize, SMEM_DYN);
    cudaFuncSetAttribute(moe_gemm_mma<false>, cudaFuncAttributeMaxDynamicSharedMemorySize, SMEM_DYN);

    k_route<<<1, 1024>>>(ids);
    k_prep<<<(N4_TOTAL + 255) / 256, 256>>>((const float4*)x, (const float4*)gup,
                                            (const float4*)dwn, (float4*)out);

    moe_gemm_mma<true ><<<dim3(F_ / 64, MAXTILES), 256, SMEM_DYN>>>(tw, out);
    moe_gemm_mma<false><<<dim3(D_ / 128, MAXTILES), 256, SMEM_DYN>>>(tw, out);
}

// round 14
// speedup vs baseline: 1.9792x; 1.0090x over previous
#include <cuda_runtime.h>
#include <cuda_fp16.h>
#include <stdint.h>

// ---------------- problem constants ----------------
namespace {
constexpr int T_  = 4096;
constexpr int D_  = 1024;
constexpr int E_  = 8;
constexpr int F_  = 2816;
constexpr int NP  = T_ * 2;       // 8192 (token,k) pairs
constexpr int N1  = 2 * F_;       // 5632
constexpr int BM  = 128;
constexpr int MAXTILES = 72;

// smem per k64-chunk buffer: 2 planes (Ah, Bh) of 128x64 fp16 = 16KB each
constexpr int PL   = 16384;
constexpr int BUF  = 2 * PL;          // 32768 per buffer
constexpr int NBUF = 3;
constexpr int SMEM_DYN = NBUF * BUF;  // 98304 (>= G2 staging 67584)

// prep region sizes (float4 units)
constexpr int N4_X   = T_ * D_ / 4;
constexpr int N4_GUP = (int)((size_t)E_ * N1 * D_ / 4);
constexpr int N4_DWN = (int)((size_t)E_ * D_ * F_ / 4);
constexpr int N4_OUT = T_ * D_ / 4;
constexpr int N4_TOTAL = N4_X + N4_GUP + N4_DWN + N4_OUT;
}

// ---------------- device scratch ----------------
__device__ __align__(16) __half g_x_hi[(size_t)T_ * D_];
__device__ __align__(16) __half g_gup_hi[(size_t)E_ * N1 * D_];
__device__ __align__(16) __half g_dwn_hi[(size_t)E_ * D_ * F_];
__device__ __align__(16) __half g_act_hi[(size_t)NP * F_];

__device__ int g_rowtok[NP];
__device__ int g_rowpair[NP];
__device__ int g_tile_e[MAXTILES];
__device__ int g_tile_r0[MAXTILES];
__device__ int g_tile_rows[MAXTILES];
__device__ int g_ntiles;

// ---------------- helpers ----------------
__device__ __forceinline__ uint32_t smem_u32(const void* p) {
    uint32_t a;
    asm("{ .reg .u64 t; cvta.to.shared.u64 t, %1; cvt.u32.u64 %0, t; }" : "=r"(a) : "l"(p));
    return a;
}
// SW128 swizzle: tile row r (0..127) = one 128B smem row; 16B unit q (0..7)
__device__ __forceinline__ uint32_t sw(int r, int q) {
    return (uint32_t)((r << 7) | (((q ^ (r & 7))) << 4));
}
__device__ __forceinline__ void hi4h(float4 v, uint32_t& h0, uint32_t& h1) {
    __half2 H0 = __floats2half2_rn(v.x, v.y);
    __half2 H1 = __floats2half2_rn(v.z, v.w);
    h0 = *(uint32_t*)&H0; h1 = *(uint32_t*)&H1;
}
__device__ __forceinline__ void ldsm4(uint32_t& r0, uint32_t& r1, uint32_t& r2, uint32_t& r3,
                                      uint32_t addr) {
    asm volatile("ldmatrix.sync.aligned.m8n8.x4.shared.b16 {%0,%1,%2,%3}, [%4];"
                 : "=r"(r0), "=r"(r1), "=r"(r2), "=r"(r3) : "r"(addr));
}
// NOTE: non-volatile — register-only op, deps carried by constraints; lets
// ptxas interleave mma with subsequent ldsm.
__device__ __forceinline__ void mma16816(float* c, const uint32_t* a, uint32_t b0, uint32_t b1) {
    asm("mma.sync.aligned.m16n8k16.row.col.f32.f16.f16.f32 "
        "{%0,%1,%2,%3}, {%4,%5,%6,%7}, {%8,%9}, {%0,%1,%2,%3};"
        : "+f"(c[0]), "+f"(c[1]), "+f"(c[2]), "+f"(c[3])
        : "r"(a[0]), "r"(a[1]), "r"(a[2]), "r"(a[3]), "r"(b0), "r"(b1));
}
__device__ __forceinline__ void cp_async16(uint32_t dst, const void* src, int sz) {
    asm volatile("cp.async.cg.shared.global [%0], [%1], 16, %2;"
                 :: "r"(dst), "l"(src), "r"(sz) : "memory");
}
__device__ __forceinline__ void cp_commit() { asm volatile("cp.async.commit_group;" ::: "memory"); }
__device__ __forceinline__ void cp_wait0()  { asm volatile("cp.async.wait_group 0;" ::: "memory"); }
__device__ __forceinline__ void cp_wait1()  { asm volatile("cp.async.wait_group 1;" ::: "memory"); }
__device__ __forceinline__ void redadd(float* p, float v) {
    asm volatile("red.global.add.f32 [%0], %1;" :: "l"(p), "f"(v) : "memory");
}

// ---------------- merged single-block routing ----------------
__global__ void k_route(const int* __restrict__ ids) {
    __shared__ int scnt[E_];
    __shared__ int soff[E_ + 1];
    const int tid = threadIdx.x;
    if (tid < E_) scnt[tid] = 0;
    __syncthreads();

    int pe[NP / 1024], ps[NP / 1024];
#pragma unroll
    for (int t = 0; t < NP / 1024; t++) {
        int p = tid + t * 1024;
        int e = ids[p];
        e = e < 0 ? 0 : (e >= E_ ? E_ - 1 : e);
        pe[t] = e;
        ps[t] = atomicAdd(&scnt[e], 1);
    }
    __syncthreads();
    if (tid == 0) {
        int off = 0;
        soff[0] = 0;
        for (int e = 0; e < E_; e++) { off += scnt[e]; soff[e + 1] = off; }
        int nt = 0;
        for (int e = 0; e < E_; e++)
            for (int r0 = soff[e]; r0 < soff[e + 1]; r0 += BM) {
                g_tile_e[nt] = e; g_tile_r0[nt] = r0;
                int rem = soff[e + 1] - r0;
                g_tile_rows[nt] = rem < BM ? rem : BM;
                nt++;
            }
        g_ntiles = nt;
    }
    __syncthreads();
#pragma unroll
    for (int t = 0; t < NP / 1024; t++) {
        int p = tid + t * 1024;
        int gr = soff[pe[t]] + ps[t];
        g_rowtok[gr]  = p >> 1;
        g_rowpair[gr] = p;
    }
}

// ---------------- merged prep: fp32 -> fp16 casts + d_out zeroing ----------------
__global__ void k_prep(const float4* __restrict__ x, const float4* __restrict__ gup,
                       const float4* __restrict__ dwn, float4* __restrict__ out) {
    int i = blockIdx.x * 256 + threadIdx.x;
    if (i < N4_X) {
        float4 v = x[i];
        uint32_t h0, h1;
        hi4h(v, h0, h1);
        ((uint2*)g_x_hi)[i] = make_uint2(h0, h1);
        return;
    }
    i -= N4_X;
    if (i < N4_GUP) {
        float4 v = gup[i];
        uint32_t h0, h1;
        hi4h(v, h0, h1);
        ((uint2*)g_gup_hi)[i] = make_uint2(h0, h1);
        return;
    }
    i -= N4_GUP;
    if (i < N4_DWN) {
        float4 v = dwn[i];
        uint32_t h0, h1;
        hi4h(v, h0, h1);
        ((uint2*)g_dwn_hi)[i] = make_uint2(h0, h1);
        return;
    }
    i -= N4_DWN;
    if (i < N4_OUT) out[i] = make_float4(0.f, 0.f, 0.f, 0.f);
}

// ---------------- pure fp16 HMMA grouped GEMM, BK=64, hoisted addressing ----
// block 128x128, 8 warps (2m x 4n), warp 64x32, occ 2, 3-stage cp.async,
// SW128 swizzle, one barrier per 64 k, prefetch issued right after barrier.
// G1: 64 j per block (128 interleaved gate/up B-rows)  KDIM=1024, NC=16
// G2: 128 n per block                                  KDIM=2816, NC=44
template <bool G1>
__global__ void __launch_bounds__(256, 2)
moe_gemm_mma(const float* __restrict__ tw, float* __restrict__ outp) {
    constexpr int KDIM = G1 ? D_ : F_;
    constexpr int NC   = KDIM / 64;

    const int bt = blockIdx.y;
    if (bt >= g_ntiles) return;

    const int e    = g_tile_e[bt];
    const int row0 = g_tile_r0[bt];
    const int rows = g_tile_rows[bt];
    const int bn0  = blockIdx.x * (G1 ? 64 : 128);

    const char* __restrict__ Ab = (const char*)(G1 ? g_x_hi : g_act_hi);
    const size_t eoff = (size_t)e * (G1 ? (size_t)N1 * D_ : (size_t)D_ * F_);
    const char* __restrict__ Bb = (const char*)((G1 ? g_gup_hi : g_dwn_hi) + eoff);

    extern __shared__ __align__(16) char dynraw[];
    const uint32_t dynbase = smem_u32(dynraw);

    __shared__ int   s_map[BM];
    __shared__ int   s_out[BM];
    __shared__ float s_wt[BM];

    const int tid  = threadIdx.x;
    const int wid  = tid >> 5;
    const int lane = tid & 31;

    if (tid < BM) {
        int amap = -1, omap = -1;
        float w = 0.f;
        if (tid < rows) {
            if (G1) { amap = g_rowtok[row0 + tid]; omap = row0 + tid; }
            else    { amap = row0 + tid;           omap = g_rowpair[row0 + tid];
                      w = tw[omap]; }
        }
        s_map[tid] = amap; s_out[tid] = omap; s_wt[tid] = w;
    }
    __syncthreads();

    // ---- hoisted cp.async addressing: 4 A units + 4 B units per thread ----
    uint32_t aoff[4], adst[4], boff[4], bdst[4];
    int asz[4];
#pragma unroll
    for (int t = 0; t < 4; t++) {
        int u = tid + t * 256;
        int row = u >> 3, q = u & 7;
        int ar = s_map[row];
        asz[t]  = ar >= 0 ? 16 : 0;
        aoff[t] = (uint32_t)((ar < 0 ? 0 : ar) * KDIM * 2 + q * 16);
        adst[t] = sw(row, q);
        int brow = G1 ? (bn0 + (row >> 1) + (row & 1) * F_) : (bn0 + row);
        boff[t] = (uint32_t)(brow * KDIM * 2 + q * 16);
        bdst[t] = PL + sw(row, q);
    }

    auto issue = [&](int c) {
        const uint32_t base = dynbase + (uint32_t)(c % NBUF) * BUF;
#pragma unroll
        for (int t = 0; t < 4; t++) {
            cp_async16(base + adst[t], Ab + aoff[t], asz[t]);
            aoff[t] += 128;
        }
#pragma unroll
        for (int t = 0; t < 4; t++) {
            cp_async16(base + bdst[t], Bb + boff[t], 16);
            boff[t] += 128;
        }
        cp_commit();
    };

    // warp tile: 64 m x 32 n
    const int wm = (wid >> 2) * 64;
    const int wn = (wid & 3) * 32;
    const int lrow  = lane & 15;
    const int qhalf = lane >> 4;     // 0/1 -> 16B half within each k32

    float acc[4][4][4];
#pragma unroll
    for (int i = 0; i < 4; i++)
#pragma unroll
        for (int j = 0; j < 4; j++)
#pragma unroll
            for (int k = 0; k < 4; k++) acc[i][j][k] = 0.f;

    issue(0);
    if (NC > 1) issue(1);

    for (int c = 0; c < NC; c++) {
        if (c + 1 < NC) cp_wait1();
        else            cp_wait0();
        __syncthreads();   // stage c visible; all warps done with stage c-1

        // prefetch c+2 immediately: buffer (c+2)%3 == (c-1)%3, released above
        if (c + 2 < NC) issue(c + 2);

        const uint32_t base = dynbase + (uint32_t)(c % NBUF) * BUF;
        const uint32_t ah = base, bh = base + PL;

#pragma unroll
        for (int kk = 0; kk < 4; kk++) {          // 4 k16 steps per 64-chunk
            const int qlog = kk * 2 + qhalf;      // 16B unit 0..7
            uint32_t bfh[2][4];
#pragma unroll
            for (int g = 0; g < 2; g++) {
                int r = wn + g * 16 + lrow;
                ldsm4(bfh[g][0], bfh[g][1], bfh[g][2], bfh[g][3], bh + sw(r, qlog));
            }
#pragma unroll
            for (int mi = 0; mi < 4; mi++) {
                int r = wm + mi * 16 + lrow;
                uint32_t afh[4];
                ldsm4(afh[0], afh[1], afh[2], afh[3], ah + sw(r, qlog));
#pragma unroll
                for (int ni = 0; ni < 4; ni++) {
                    const int g = ni >> 1, sub = ni & 1;
                    mma16816(acc[mi][ni], afh, bfh[g][sub], bfh[g][sub + 2]);
                }
            }
        }
    }
    __syncthreads();

    // ---- epilogue (smem reused for staging) ----
    float* stg = (float*)dynraw;
    const int group = lane >> 2;
    const int tig   = lane & 3;

    if (G1) {
#pragma unroll
        for (int mi = 0; mi < 4; mi++) {
            int m = wm + mi * 16 + group;
#pragma unroll
            for (int ni = 0; ni < 4; ni++) {
                int j = (wid & 3) * 16 + ni * 4 + tig;
                float g0 = acc[mi][ni][0], u0 = acc[mi][ni][1];
                float g1 = acc[mi][ni][2], u1 = acc[mi][ni][3];
                stg[m * 68 + j]       = g0 / (1.f + __expf(-g0)) * u0;
                stg[(m + 8) * 68 + j] = g1 / (1.f + __expf(-g1)) * u1;
            }
        }
        __syncthreads();
#pragma unroll
        for (int t = 0; t < 8; t++) {
            int idx = tid + t * 256;
            int row = idx >> 4, q = idx & 15;
            int orow = s_out[row];
            if (orow >= 0) {
                float4 v = *(const float4*)(stg + row * 68 + q * 4);
                uint32_t h0, h1;
                hi4h(v, h0, h1);
                size_t ob = ((size_t)orow * F_ + bn0 + q * 4) * 2;
                *(uint2*)((char*)g_act_hi + ob) = make_uint2(h0, h1);
            }
        }
    } else {
        // stage C, weighted red.global.add into out[tok] (2 contributions/elem)
#pragma unroll
        for (int mi = 0; mi < 4; mi++) {
            int m = wm + mi * 16 + group;
#pragma unroll
            for (int ni = 0; ni < 4; ni++) {
                int n = wn + ni * 8 + tig * 2;
                *(float2*)(stg + m * 132 + n)       = make_float2(acc[mi][ni][0], acc[mi][ni][1]);
                *(float2*)(stg + (m + 8) * 132 + n) = make_float2(acc[mi][ni][2], acc[mi][ni][3]);
            }
        }
        __syncthreads();
#pragma unroll
        for (int t = 0; t < 16; t++) {
            int idx = tid + t * 256;
            int row = idx >> 5, q = idx & 31;
            int orow = s_out[row];
            if (orow >= 0) {
                float4 v = *(const float4*)(stg + row * 132 + q * 4);
                float w = s_wt[row];
                float* op = outp + (size_t)(orow >> 1) * D_ + bn0 + q * 4;
                redadd(op + 0, w * v.x);
                redadd(op + 1, w * v.y);
                redadd(op + 2, w * v.z);
                redadd(op + 3, w * v.w);
            }
        }
    }
}

// ---------------- launch ----------------
extern "C" void kernel_launch(void* const* d_in, const int* in_sizes, int n_in,
                              void* d_out, int out_size) {
    const float* x   = (const float*)d_in[0];
    const float* gup = (const float*)d_in[1];
    const float* dwn = (const float*)d_in[2];
    const float* tw  = (const float*)d_in[3];
    const int*   ids = (const int*)d_in[4];
    float* out = (float*)d_out;

    cudaFuncSetAttribute(moe_gemm_mma<true>,  cudaFuncAttributeMaxDynamicSharedMemorySize, SMEM_DYN);
    cudaFuncSetAttribute(moe_gemm_mma<false>, cudaFuncAttributeMaxDynamicSharedMemorySize, SMEM_DYN);

    k_route<<<1, 1024>>>(ids);
    k_prep<<<(N4_TOTAL + 255) / 256, 256>>>((const float4*)x, (const float4*)gup,
                                            (const float4*)dwn, (float4*)out);

    moe_gemm_mma<true ><<<dim3(F_ / 64, MAXTILES), 256, SMEM_DYN>>>(tw, out);
    moe_gemm_mma<false><<<dim3(D_ / 128, MAXTILES), 256, SMEM_DYN>>>(tw, out);
}